// round 3
// baseline (speedup 1.0000x reference)
#include <cuda_runtime.h>
#include <math.h>

// ---------------------------------------------------------------------------
// Problem constants
//   B=8, L=512, D=1024, H=16, DH=64
//   inputs (metadata order): text, image, Wq, bq, Wk, bk, Wv, bv, Wo, bo,
//                            W1, b1, W2, b2
//   outputs (flattened, in tuple order):
//     text_cross   [8,512,1024]  -> d_out + 0         (4,194,304)
//     image_cross  [8,512,1024]  -> d_out + 4,194,304
//     comp_output  [8,512,1024]  -> d_out + 8,388,608
//     avg_attn     [8,512,512]   -> d_out + 12,582,912 (2,097,152)
// ---------------------------------------------------------------------------

#define NELEM_PROJ (4194304ul)            // B*H*L*DH = 8*16*512*64

// scratch (device globals: allocation-free rule)
__device__ float g_proj[6ul * NELEM_PROJ];          // [src(2)][proj(3)][b,h,l,dh]  96MB
__device__ float g_S[128ul * 512ul * 512ul];        // [bh][q][k]                  128MB
__device__ float g_ctx[2ul * NELEM_PROJ];           // [dir][b*512+l][1024]         32MB
__device__ float g_hidden[NELEM_PROJ];              // [4096][1024]                 16MB

// ---------------------------------------------------------------------------
// Kernel 1: fused QKV projection for both modalities.
//   C[8192, 3072] = [text; image] @ [Wq|Wk|Wv] + bias, sigmoid on Q,K parts,
//   scattered into per-head layout g_proj[src][proj][b,h,l,dh].
//   grid (24, 64): x = n-tile (bsel = x/8), y = m-tile (src = y/32)
// ---------------------------------------------------------------------------
__global__ __launch_bounds__(256) void k_proj(
    const float* __restrict__ text, const float* __restrict__ image,
    const float* __restrict__ Wq, const float* __restrict__ Wk,
    const float* __restrict__ Wv,
    const float* __restrict__ bq, const float* __restrict__ bk,
    const float* __restrict__ bv)
{
    __shared__ float As[8][128];
    __shared__ float Bs[8][128];
    const int tid = threadIdx.x;

    const int src  = blockIdx.y >> 5;
    const int m0   = (blockIdx.y & 31) * 128;          // local row in [0,4096)
    const int bsel = blockIdx.x >> 3;                  // 0=Q 1=K 2=V
    const int n0   = (blockIdx.x & 7) * 128;           // local col in [0,1024)

    const float* __restrict__ A  = src ? image : text;
    const float* __restrict__ W  = (bsel == 0) ? Wq : (bsel == 1 ? Wk : Wv);
    const float* __restrict__ bb = (bsel == 0) ? bq : (bsel == 1 ? bk : bv);

    const int arow = tid >> 1, ak = (tid & 1) * 4;
    const int brow = tid >> 5, bn4 = (tid & 31) * 4;
    const float* Aptr = A + (size_t)(m0 + arow) * 1024 + ak;
    const float* Bptr = W + (size_t)brow * 1024 + n0 + bn4;

    float acc[8][8];
    #pragma unroll
    for (int i = 0; i < 8; ++i)
        #pragma unroll
        for (int j = 0; j < 8; ++j) acc[i][j] = 0.f;

    const int ty8 = (tid >> 4) * 8, tx8 = (tid & 15) * 8;

    for (int k0 = 0; k0 < 1024; k0 += 8) {
        float4 a = *(const float4*)(Aptr + k0);
        As[ak + 0][arow] = a.x; As[ak + 1][arow] = a.y;
        As[ak + 2][arow] = a.z; As[ak + 3][arow] = a.w;
        float4 b = *(const float4*)(Bptr + (size_t)k0 * 1024);
        *(float4*)&Bs[brow][bn4] = b;
        __syncthreads();
        #pragma unroll
        for (int kk = 0; kk < 8; ++kk) {
            float ar[8], br[8];
            #pragma unroll
            for (int i = 0; i < 8; ++i) ar[i] = As[kk][ty8 + i];
            #pragma unroll
            for (int j = 0; j < 8; ++j) br[j] = Bs[kk][tx8 + j];
            #pragma unroll
            for (int i = 0; i < 8; ++i)
                #pragma unroll
                for (int j = 0; j < 8; ++j) acc[i][j] += ar[i] * br[j];
        }
        __syncthreads();
    }

    float* dst = g_proj + (size_t)(src * 3 + bsel) * NELEM_PROJ;
    #pragma unroll
    for (int i = 0; i < 8; ++i) {
        const int m = m0 + ty8 + i;
        const int bidx = m >> 9, l = m & 511;
        #pragma unroll
        for (int j = 0; j < 8; ++j) {
            const int nl = n0 + tx8 + j;
            float v = acc[i][j] + bb[nl];
            if (bsel < 2) v = 1.f / (1.f + __expf(-v));   // sigmoid membership
            const int h = nl >> 6, dh = nl & 63;
            dst[(size_t)((bidx * 16 + h) * 512 + l) * 64 + dh] = v;
        }
    }
}

// ---------------------------------------------------------------------------
// Kernel 2: batched scores  S[bh][q][k] = (1/64) * muQ[bh][q][:] . muK[bh][k][:]
//   NT GEMM M=512 N=512 K=64 per bh.  grid (4, 4, 128)
// ---------------------------------------------------------------------------
__global__ __launch_bounds__(256) void k_scores(int dir)
{
    __shared__ float As[8][128];
    __shared__ float Bs[8][128];
    const int tid = threadIdx.x;
    const int bh = blockIdx.z;
    const int m0 = blockIdx.y * 128;
    const int n0 = blockIdx.x * 128;

    const int q_src = dir ? 1 : 0;       // dir0: Q from text, K from image
    const int k_src = dir ? 0 : 1;
    const float* __restrict__ Q = g_proj + (size_t)(q_src * 3 + 0) * NELEM_PROJ
                                  + (size_t)bh * 512 * 64;
    const float* __restrict__ Kp = g_proj + (size_t)(k_src * 3 + 1) * NELEM_PROJ
                                  + (size_t)bh * 512 * 64;
    float* __restrict__ C = g_S + (size_t)bh * 262144;

    const int arow = tid >> 1, ak = (tid & 1) * 4;
    const float* Aptr = Q  + (size_t)(m0 + arow) * 64 + ak;
    const float* Bptr = Kp + (size_t)(n0 + arow) * 64 + ak;

    float acc[8][8];
    #pragma unroll
    for (int i = 0; i < 8; ++i)
        #pragma unroll
        for (int j = 0; j < 8; ++j) acc[i][j] = 0.f;

    const int ty8 = (tid >> 4) * 8, tx8 = (tid & 15) * 8;

    for (int k0 = 0; k0 < 64; k0 += 8) {
        float4 a = *(const float4*)(Aptr + k0);
        As[ak + 0][arow] = a.x; As[ak + 1][arow] = a.y;
        As[ak + 2][arow] = a.z; As[ak + 3][arow] = a.w;
        float4 b = *(const float4*)(Bptr + k0);
        Bs[ak + 0][arow] = b.x; Bs[ak + 1][arow] = b.y;
        Bs[ak + 2][arow] = b.z; Bs[ak + 3][arow] = b.w;
        __syncthreads();
        #pragma unroll
        for (int kk = 0; kk < 8; ++kk) {
            float ar[8], br[8];
            #pragma unroll
            for (int i = 0; i < 8; ++i) ar[i] = As[kk][ty8 + i];
            #pragma unroll
            for (int j = 0; j < 8; ++j) br[j] = Bs[kk][tx8 + j];
            #pragma unroll
            for (int i = 0; i < 8; ++i)
                #pragma unroll
                for (int j = 0; j < 8; ++j) acc[i][j] += ar[i] * br[j];
        }
        __syncthreads();
    }

    #pragma unroll
    for (int i = 0; i < 8; ++i)
        #pragma unroll
        for (int j = 0; j < 8; ++j)
            C[(size_t)(m0 + ty8 + i) * 512 + n0 + tx8 + j] = acc[i][j] * 0.015625f;
}

// ---------------------------------------------------------------------------
// Kernel 3: row softmax over g_S (65536 rows of 512). One warp per row.
// ---------------------------------------------------------------------------
__global__ __launch_bounds__(256) void k_softmax()
{
    const int row  = blockIdx.x * 8 + (threadIdx.x >> 5);
    const int lane = threadIdx.x & 31;
    float* p = g_S + (size_t)row * 512;

    float v[16];
    float mx = -1e30f;
    #pragma unroll
    for (int i = 0; i < 16; ++i) { v[i] = p[lane + i * 32]; mx = fmaxf(mx, v[i]); }
    #pragma unroll
    for (int o = 16; o > 0; o >>= 1) mx = fmaxf(mx, __shfl_xor_sync(0xffffffffu, mx, o));
    float s = 0.f;
    #pragma unroll
    for (int i = 0; i < 16; ++i) { v[i] = __expf(v[i] - mx); s += v[i]; }
    #pragma unroll
    for (int o = 16; o > 0; o >>= 1) s += __shfl_xor_sync(0xffffffffu, s, o);
    const float inv = 1.f / s;
    #pragma unroll
    for (int i = 0; i < 16; ++i) p[lane + i * 32] = v[i] * inv;
}

// ---------------------------------------------------------------------------
// Kernel 4: O = P @ V per bh, scattered to g_ctx[dir][b*512+l][h*64+dh]
//   GEMM M=512 N=64 K=512, BM=128 BN=64 BK=16, TM=8 TN=4.  grid (4, 128)
// ---------------------------------------------------------------------------
__global__ __launch_bounds__(256) void k_pv(int dir)
{
    __shared__ float As[16][128];
    __shared__ float Bs[16][64];
    const int tid = threadIdx.x;
    const int bh = blockIdx.y;
    const int m0 = blockIdx.x * 128;

    const int k_src = dir ? 0 : 1;       // V comes from same modality as K
    const float* __restrict__ P = g_S + (size_t)bh * 262144;
    const float* __restrict__ V = g_proj + (size_t)(k_src * 3 + 2) * NELEM_PROJ
                                  + (size_t)bh * 512 * 64;

    const int arow = tid >> 1, ak = (tid & 1) * 8;
    const int brow = tid >> 4, bn4 = (tid & 15) * 4;

    float acc[8][4];
    #pragma unroll
    for (int i = 0; i < 8; ++i)
        #pragma unroll
        for (int j = 0; j < 4; ++j) acc[i][j] = 0.f;

    const int ty8 = (tid >> 4) * 8, tx4 = (tid & 15) * 4;

    for (int k0 = 0; k0 < 512; k0 += 16) {
        float4 a0 = *(const float4*)(P + (size_t)(m0 + arow) * 512 + k0 + ak);
        float4 a1 = *(const float4*)(P + (size_t)(m0 + arow) * 512 + k0 + ak + 4);
        As[ak + 0][arow] = a0.x; As[ak + 1][arow] = a0.y;
        As[ak + 2][arow] = a0.z; As[ak + 3][arow] = a0.w;
        As[ak + 4][arow] = a1.x; As[ak + 5][arow] = a1.y;
        As[ak + 6][arow] = a1.z; As[ak + 7][arow] = a1.w;
        *(float4*)&Bs[brow][bn4] = *(const float4*)(V + (size_t)(k0 + brow) * 64 + bn4);
        __syncthreads();
        #pragma unroll
        for (int kk = 0; kk < 16; ++kk) {
            float ar[8], br[4];
            #pragma unroll
            for (int i = 0; i < 8; ++i) ar[i] = As[kk][ty8 + i];
            #pragma unroll
            for (int j = 0; j < 4; ++j) br[j] = Bs[kk][tx4 + j];
            #pragma unroll
            for (int i = 0; i < 8; ++i)
                #pragma unroll
                for (int j = 0; j < 4; ++j) acc[i][j] += ar[i] * br[j];
        }
        __syncthreads();
    }

    const int b = bh >> 4, h = bh & 15;
    float* dst = g_ctx + (size_t)dir * NELEM_PROJ;
    #pragma unroll
    for (int i = 0; i < 8; ++i) {
        const int l = m0 + ty8 + i;
        #pragma unroll
        for (int j = 0; j < 4; ++j)
            dst[(size_t)(b * 512 + l) * 1024 + h * 64 + tx4 + j] = acc[i][j];
    }
}

// ---------------------------------------------------------------------------
// Kernel 5: avg_attn[b][q][k] = mean over h of P  (reads dir-0 probs in g_S)
// ---------------------------------------------------------------------------
__global__ __launch_bounds__(256) void k_avg(float* __restrict__ out)
{
    const int e = blockIdx.x * 256 + threadIdx.x;    // 2,097,152 total
    const int b = e >> 18;
    const int r = e & 262143;
    float s = 0.f;
    #pragma unroll
    for (int h = 0; h < 16; ++h)
        s += g_S[(size_t)(b * 16 + h) * 262144 + r];
    out[e] = s * 0.0625f;
}

// ---------------------------------------------------------------------------
// Kernel 6: generic NN GEMM, N=1024 fixed, optional relu.
//   C[M,1024] = A[M,K] @ Bm[K,1024] + bias.  grid (8, M/128)
// ---------------------------------------------------------------------------
__global__ __launch_bounds__(256) void k_gemm_nn(
    const float* __restrict__ A, const float* __restrict__ Bm,
    const float* __restrict__ bias, float* __restrict__ C, int K, int relu)
{
    __shared__ float As[8][128];
    __shared__ float Bs[8][128];
    const int tid = threadIdx.x;
    const int m0 = blockIdx.y * 128;
    const int n0 = blockIdx.x * 128;

    const int arow = tid >> 1, ak = (tid & 1) * 4;
    const int brow = tid >> 5, bn4 = (tid & 31) * 4;
    const float* Aptr = A  + (size_t)(m0 + arow) * K + ak;
    const float* Bptr = Bm + (size_t)brow * 1024 + n0 + bn4;

    float acc[8][8];
    #pragma unroll
    for (int i = 0; i < 8; ++i)
        #pragma unroll
        for (int j = 0; j < 8; ++j) acc[i][j] = 0.f;

    const int ty8 = (tid >> 4) * 8, tx8 = (tid & 15) * 8;

    for (int k0 = 0; k0 < K; k0 += 8) {
        float4 a = *(const float4*)(Aptr + k0);
        As[ak + 0][arow] = a.x; As[ak + 1][arow] = a.y;
        As[ak + 2][arow] = a.z; As[ak + 3][arow] = a.w;
        float4 b = *(const float4*)(Bptr + (size_t)k0 * 1024);
        *(float4*)&Bs[brow][bn4] = b;
        __syncthreads();
        #pragma unroll
        for (int kk = 0; kk < 8; ++kk) {
            float ar[8], br[8];
            #pragma unroll
            for (int i = 0; i < 8; ++i) ar[i] = As[kk][ty8 + i];
            #pragma unroll
            for (int j = 0; j < 8; ++j) br[j] = Bs[kk][tx8 + j];
            #pragma unroll
            for (int i = 0; i < 8; ++i)
                #pragma unroll
                for (int j = 0; j < 8; ++j) acc[i][j] += ar[i] * br[j];
        }
        __syncthreads();
    }

    #pragma unroll
    for (int i = 0; i < 8; ++i) {
        const int m = m0 + ty8 + i;
        #pragma unroll
        for (int j = 0; j < 8; ++j) {
            const int n = n0 + tx8 + j;
            float v = acc[i][j] + bias[n];
            if (relu) v = fmaxf(v, 0.f);
            C[(size_t)m * 1024 + n] = v;
        }
    }
}

// ---------------------------------------------------------------------------
// Kernel 7: FFN1 — A is concat(text, image, text_cross) along features.
//   hidden[4096,1024] = relu(A[4096,3072] @ W1 + b1).  grid (8, 32)
// ---------------------------------------------------------------------------
__global__ __launch_bounds__(256) void k_ffn1(
    const float* __restrict__ text, const float* __restrict__ image,
    const float* __restrict__ tcross, const float* __restrict__ W1,
    const float* __restrict__ b1)
{
    __shared__ float As[8][128];
    __shared__ float Bs[8][128];
    const int tid = threadIdx.x;
    const int m0 = blockIdx.y * 128;
    const int n0 = blockIdx.x * 128;

    const int arow = tid >> 1, ak = (tid & 1) * 4;
    const int brow = tid >> 5, bn4 = (tid & 31) * 4;
    const float* Bptr = W1 + (size_t)brow * 1024 + n0 + bn4;

    float acc[8][8];
    #pragma unroll
    for (int i = 0; i < 8; ++i)
        #pragma unroll
        for (int j = 0; j < 8; ++j) acc[i][j] = 0.f;

    const int ty8 = (tid >> 4) * 8, tx8 = (tid & 15) * 8;

    for (int k0 = 0; k0 < 3072; k0 += 8) {
        const int kg = k0 + ak;
        const int seg = kg >> 10, kl = kg & 1023;
        const float* Ap = (seg == 0) ? text : (seg == 1 ? image : tcross);
        float4 a = *(const float4*)(Ap + (size_t)(m0 + arow) * 1024 + kl);
        As[ak + 0][arow] = a.x; As[ak + 1][arow] = a.y;
        As[ak + 2][arow] = a.z; As[ak + 3][arow] = a.w;
        float4 b = *(const float4*)(Bptr + (size_t)k0 * 1024);
        *(float4*)&Bs[brow][bn4] = b;
        __syncthreads();
        #pragma unroll
        for (int kk = 0; kk < 8; ++kk) {
            float ar[8], br[8];
            #pragma unroll
            for (int i = 0; i < 8; ++i) ar[i] = As[kk][ty8 + i];
            #pragma unroll
            for (int j = 0; j < 8; ++j) br[j] = Bs[kk][tx8 + j];
            #pragma unroll
            for (int i = 0; i < 8; ++i)
                #pragma unroll
                for (int j = 0; j < 8; ++j) acc[i][j] += ar[i] * br[j];
        }
        __syncthreads();
    }

    #pragma unroll
    for (int i = 0; i < 8; ++i) {
        const int m = m0 + ty8 + i;
        #pragma unroll
        for (int j = 0; j < 8; ++j) {
            const int n = n0 + tx8 + j;
            g_hidden[(size_t)m * 1024 + n] = fmaxf(acc[i][j] + b1[n], 0.f);
        }
    }
}

// ---------------------------------------------------------------------------
// launch
// ---------------------------------------------------------------------------
extern "C" void kernel_launch(void* const* d_in, const int* in_sizes, int n_in,
                              void* d_out, int out_size)
{
    const float* text  = (const float*)d_in[0];
    const float* image = (const float*)d_in[1];
    const float* Wq = (const float*)d_in[2];
    const float* bq = (const float*)d_in[3];
    const float* Wk = (const float*)d_in[4];
    const float* bk = (const float*)d_in[5];
    const float* Wv = (const float*)d_in[6];
    const float* bv = (const float*)d_in[7];
    const float* Wo = (const float*)d_in[8];
    const float* bo = (const float*)d_in[9];
    const float* W1 = (const float*)d_in[10];
    const float* b1 = (const float*)d_in[11];
    const float* W2 = (const float*)d_in[12];
    const float* b2 = (const float*)d_in[13];
    float* out = (float*)d_out;

    float* ctx_p = 0;
    float* hidden_p = 0;
    cudaGetSymbolAddress((void**)&ctx_p, g_ctx);
    cudaGetSymbolAddress((void**)&hidden_p, g_hidden);

    // 1) fused QKV projections (both modalities) + sigmoid memberships
    k_proj<<<dim3(24, 64), 256>>>(text, image, Wq, Wk, Wv, bq, bk, bv);

    // 2) direction 0: text queries image
    k_scores<<<dim3(4, 4, 128), 256>>>(0);
    k_softmax<<<8192, 256>>>();
    k_pv<<<dim3(4, 128), 256>>>(0);
    k_avg<<<8192, 256>>>(out + 12582912);   // avg_attn from dir-0 probs

    // 3) direction 1: image queries text (reuses g_S)
    k_scores<<<dim3(4, 4, 128), 256>>>(1);
    k_softmax<<<8192, 256>>>();
    k_pv<<<dim3(4, 128), 256>>>(1);

    // 4) output projection: [ctx_text; ctx_image] @ Wo + bo ->
    //    text_cross | image_cross directly in d_out
    k_gemm_nn<<<dim3(8, 64), 256>>>(ctx_p, Wo, bo, out, 1024, 0);

    // 5) FFN over concat(text, image, text_cross)
    k_ffn1<<<dim3(8, 32), 256>>>(text, image, out, W1, b1);
    k_gemm_nn<<<dim3(8, 32), 256>>>(hidden_p, W2, b2, out + 8388608, 1024, 0);
}

// round 4
// speedup vs baseline: 1.8929x; 1.8929x over previous
#include <cuda_runtime.h>
#include <math.h>
#include <stdint.h>

// ---------------------------------------------------------------------------
// Problem constants
//   B=8, L=512, D=1024, H=16, DH=64
//   outputs: text_cross[4M] | image_cross[4M] | comp_out[4M] | avg_attn[2M]
// ---------------------------------------------------------------------------

#define NELEM_PROJ (4194304ul)            // B*H*L*DH

// scratch (device globals: allocation-free rule)
__device__ float g_proj[6ul * NELEM_PROJ];          // [src(2)][proj(3)][b,h,l,dh]
__device__ float g_S[128ul * 512ul * 512ul];        // [bh][q][k]
__device__ float g_ctx[2ul * NELEM_PROJ];           // [dir][b*512+l][1024]
__device__ float g_hidden[NELEM_PROJ];              // [4096][1024]

// ---------------------------------------------------------------------------
// tf32 helpers
// ---------------------------------------------------------------------------
__device__ __forceinline__ uint32_t f2tf32(float f) {
    uint32_t u;
    asm("cvt.rna.tf32.f32 %0, %1;" : "=r"(u) : "f"(f));
    return u;
}

#define MMA_TF32(d, a, b)                                                     \
    asm volatile(                                                             \
        "mma.sync.aligned.m16n8k8.row.col.f32.tf32.tf32.f32 "                 \
        "{%0,%1,%2,%3}, {%4,%5,%6,%7}, {%8,%9}, {%0,%1,%2,%3};"               \
        : "+f"(d[0]), "+f"(d[1]), "+f"(d[2]), "+f"(d[3])                      \
        : "r"(a[0]), "r"(a[1]), "r"(a[2]), "r"(a[3]), "r"(b[0]), "r"(b[1]))

// ---------------------------------------------------------------------------
// Tensor-core tf32 GEMM, BM=BN=128, BK=16, 256 threads (8 warps, 2x4),
// warp tile 32x64, mma m16n8k8.
//   AMODE 0: A = A0[M][1024] row-major
//   AMODE 1: A = concat(A0,A1,A2) along K (each [M][1024]); K=3072
//   AMODE 2: A = rows 0..4095 from A0, 4096..8191 from A1 (proj)
//   EMODE 0: C[r*1024+c] = acc + bias[c] (relu opt)
//   EMODE 1: proj epilogue: sigmoid for bsel<2, scatter to g_proj head layout
// For AMODE 2 the x-grid covers 24 n-tiles: bsel = x>>3 selects W/bias.
// ---------------------------------------------------------------------------
template<int AMODE, int EMODE>
__global__ __launch_bounds__(256) void k_tc(
    const float* __restrict__ A0, const float* __restrict__ A1,
    const float* __restrict__ A2,
    const float* __restrict__ Wa, const float* __restrict__ Wb,
    const float* __restrict__ Wc,
    const float* __restrict__ ba, const float* __restrict__ bbv,
    const float* __restrict__ bc,
    float* __restrict__ C, int K, int relu)
{
    __shared__ __align__(16) uint32_t As[2][128][20];
    __shared__ __align__(16) uint32_t Bs[2][16][136];

    const int tid  = threadIdx.x;
    const int wid  = tid >> 5, lane = tid & 31;
    const int gid  = lane >> 2, tig = lane & 3;
    const int wm   = (wid & 3) * 32;       // warp row base in tile
    const int wn   = (wid >> 2) * 64;      // warp col base in tile

    int bsel = 0, n0;
    const float* W;
    const float* bias;
    if (AMODE == 2) {
        bsel = blockIdx.x >> 3;
        n0   = (blockIdx.x & 7) * 128;
        W    = (bsel == 0) ? Wa : (bsel == 1 ? Wb : Wc);
        bias = (bsel == 0) ? ba : (bsel == 1 ? bbv : bc);
    } else {
        n0 = blockIdx.x * 128;
        W = Wa; bias = ba;
    }
    const int m0 = blockIdx.y * 128;

    float acc[2][8][4];
    #pragma unroll
    for (int i = 0; i < 2; ++i)
        #pragma unroll
        for (int j = 0; j < 8; ++j)
            #pragma unroll
            for (int q = 0; q < 4; ++q) acc[i][j][q] = 0.f;

    float4 pa[2], pb[2];
    const int T = K >> 4;

    // ---- prologue: load tile 0 ----
    #pragma unroll
    for (int i = 0; i < 2; ++i) {
        const int idx = tid * 2 + i;
        const int row = idx >> 2, kc = idx & 3;
        const float* Ap;
        int col = kc * 4;
        if (AMODE == 1) { Ap = A0 + (size_t)(m0 + row) * 1024; }
        else if (AMODE == 2) {
            const int m = m0 + row;
            Ap = ((m >> 12) ? A1 : A0) + (size_t)(m & 4095) * 1024;
        } else { Ap = A0 + (size_t)(m0 + row) * 1024; }
        pa[i] = *(const float4*)(Ap + col);
        const int brow = idx >> 5, nc = idx & 31;
        pb[i] = *(const float4*)(W + (size_t)brow * 1024 + n0 + nc * 4);
    }
    #pragma unroll
    for (int i = 0; i < 2; ++i) {
        const int idx = tid * 2 + i;
        const int row = idx >> 2, kc = idx & 3;
        As[0][row][kc * 4 + 0] = f2tf32(pa[i].x);
        As[0][row][kc * 4 + 1] = f2tf32(pa[i].y);
        As[0][row][kc * 4 + 2] = f2tf32(pa[i].z);
        As[0][row][kc * 4 + 3] = f2tf32(pa[i].w);
        const int brow = idx >> 5, nc = idx & 31;
        uint4 bv;
        bv.x = f2tf32(pb[i].x); bv.y = f2tf32(pb[i].y);
        bv.z = f2tf32(pb[i].z); bv.w = f2tf32(pb[i].w);
        *(uint4*)&Bs[0][brow][nc * 4] = bv;
    }
    __syncthreads();

    // ---- main loop ----
    for (int t = 0; t < T; ++t) {
        // prefetch next tile into registers
        if (t + 1 < T) {
            const int k0 = (t + 1) * 16;
            #pragma unroll
            for (int i = 0; i < 2; ++i) {
                const int idx = tid * 2 + i;
                const int row = idx >> 2, kc = idx & 3;
                const float* Ap;
                int col = k0 + kc * 4;
                if (AMODE == 1) {
                    const int seg = k0 >> 10;
                    Ap = (seg == 0) ? A0 : (seg == 1 ? A1 : A2);
                    Ap += (size_t)(m0 + row) * 1024;
                    col = (k0 & 1023) + kc * 4;
                } else if (AMODE == 2) {
                    const int m = m0 + row;
                    Ap = ((m >> 12) ? A1 : A0) + (size_t)(m & 4095) * 1024;
                } else {
                    Ap = A0 + (size_t)(m0 + row) * 1024;
                }
                pa[i] = *(const float4*)(Ap + col);
                const int brow = idx >> 5, nc = idx & 31;
                pb[i] = *(const float4*)(W + (size_t)(k0 + brow) * 1024 + n0 + nc * 4);
            }
        }

        // compute on buffer t&1
        const int buf = t & 1;
        #pragma unroll
        for (int kk = 0; kk < 16; kk += 8) {
            uint32_t af[2][4], bf[8][2];
            #pragma unroll
            for (int tm = 0; tm < 2; ++tm) {
                const int mb = wm + tm * 16;
                af[tm][0] = As[buf][mb + gid    ][kk + tig    ];
                af[tm][1] = As[buf][mb + gid + 8][kk + tig    ];
                af[tm][2] = As[buf][mb + gid    ][kk + tig + 4];
                af[tm][3] = As[buf][mb + gid + 8][kk + tig + 4];
            }
            #pragma unroll
            for (int tn = 0; tn < 8; ++tn) {
                const int nb = wn + tn * 8;
                bf[tn][0] = Bs[buf][kk + tig    ][nb + gid];
                bf[tn][1] = Bs[buf][kk + tig + 4][nb + gid];
            }
            #pragma unroll
            for (int tm = 0; tm < 2; ++tm)
                #pragma unroll
                for (int tn = 0; tn < 8; ++tn)
                    MMA_TF32(acc[tm][tn], af[tm], bf[tn]);
        }

        // store prefetched tile into the other buffer
        if (t + 1 < T) {
            const int nbuf = (t + 1) & 1;
            #pragma unroll
            for (int i = 0; i < 2; ++i) {
                const int idx = tid * 2 + i;
                const int row = idx >> 2, kc = idx & 3;
                As[nbuf][row][kc * 4 + 0] = f2tf32(pa[i].x);
                As[nbuf][row][kc * 4 + 1] = f2tf32(pa[i].y);
                As[nbuf][row][kc * 4 + 2] = f2tf32(pa[i].z);
                As[nbuf][row][kc * 4 + 3] = f2tf32(pa[i].w);
                const int brow = idx >> 5, nc = idx & 31;
                uint4 bv;
                bv.x = f2tf32(pb[i].x); bv.y = f2tf32(pb[i].y);
                bv.z = f2tf32(pb[i].z); bv.w = f2tf32(pb[i].w);
                *(uint4*)&Bs[nbuf][brow][nc * 4] = bv;
            }
        }
        __syncthreads();
    }

    // ---- epilogue ----
    if (EMODE == 0) {
        #pragma unroll
        for (int tm = 0; tm < 2; ++tm) {
            #pragma unroll
            for (int tn = 0; tn < 8; ++tn) {
                const int r = m0 + wm + tm * 16 + gid;
                const int c = n0 + wn + tn * 8 + 2 * tig;
                float v0 = acc[tm][tn][0] + bias[c];
                float v1 = acc[tm][tn][1] + bias[c + 1];
                float v2 = acc[tm][tn][2] + bias[c];
                float v3 = acc[tm][tn][3] + bias[c + 1];
                if (relu) {
                    v0 = fmaxf(v0, 0.f); v1 = fmaxf(v1, 0.f);
                    v2 = fmaxf(v2, 0.f); v3 = fmaxf(v3, 0.f);
                }
                *(float2*)&C[(size_t)r * 1024 + c]       = make_float2(v0, v1);
                *(float2*)&C[(size_t)(r + 8) * 1024 + c] = make_float2(v2, v3);
            }
        }
    } else {
        const int src = m0 >> 12;            // all rows in tile share src
        float* dst = g_proj + (size_t)(src * 3 + bsel) * NELEM_PROJ;
        #pragma unroll
        for (int tm = 0; tm < 2; ++tm) {
            #pragma unroll
            for (int tn = 0; tn < 8; ++tn) {
                const int m  = m0 + wm + tm * 16 + gid;
                const int lr = m & 4095;
                const int bidx = lr >> 9;
                const int l    = lr & 511;
                const int nl = n0 + wn + tn * 8 + 2 * tig;
                const int h = nl >> 6, dh = nl & 63;
                float v0 = acc[tm][tn][0] + bias[nl];
                float v1 = acc[tm][tn][1] + bias[nl + 1];
                float v2 = acc[tm][tn][2] + bias[nl];
                float v3 = acc[tm][tn][3] + bias[nl + 1];
                if (bsel < 2) {
                    v0 = 1.f / (1.f + __expf(-v0));
                    v1 = 1.f / (1.f + __expf(-v1));
                    v2 = 1.f / (1.f + __expf(-v2));
                    v3 = 1.f / (1.f + __expf(-v3));
                }
                const size_t base0 = (size_t)((bidx * 16 + h) * 512 + l) * 64 + dh;
                const size_t base1 = (size_t)((bidx * 16 + h) * 512 + l + 8) * 64 + dh;
                *(float2*)&dst[base0] = make_float2(v0, v1);
                *(float2*)&dst[base1] = make_float2(v2, v3);
            }
        }
    }
}

// ---------------------------------------------------------------------------
// Attention kernels (SIMT fp32, unchanged from passing baseline)
// ---------------------------------------------------------------------------
__global__ __launch_bounds__(256) void k_scores(int dir)
{
    __shared__ float As[8][128];
    __shared__ float Bs[8][128];
    const int tid = threadIdx.x;
    const int bh = blockIdx.z;
    const int m0 = blockIdx.y * 128;
    const int n0 = blockIdx.x * 128;

    const int q_src = dir ? 1 : 0;
    const int k_src = dir ? 0 : 1;
    const float* __restrict__ Q = g_proj + (size_t)(q_src * 3 + 0) * NELEM_PROJ
                                  + (size_t)bh * 512 * 64;
    const float* __restrict__ Kp = g_proj + (size_t)(k_src * 3 + 1) * NELEM_PROJ
                                  + (size_t)bh * 512 * 64;
    float* __restrict__ C = g_S + (size_t)bh * 262144;

    const int arow = tid >> 1, ak = (tid & 1) * 4;
    const float* Aptr = Q  + (size_t)(m0 + arow) * 64 + ak;
    const float* Bptr = Kp + (size_t)(n0 + arow) * 64 + ak;

    float acc[8][8];
    #pragma unroll
    for (int i = 0; i < 8; ++i)
        #pragma unroll
        for (int j = 0; j < 8; ++j) acc[i][j] = 0.f;

    const int ty8 = (tid >> 4) * 8, tx8 = (tid & 15) * 8;

    for (int k0 = 0; k0 < 64; k0 += 8) {
        float4 a = *(const float4*)(Aptr + k0);
        As[ak + 0][arow] = a.x; As[ak + 1][arow] = a.y;
        As[ak + 2][arow] = a.z; As[ak + 3][arow] = a.w;
        float4 b = *(const float4*)(Bptr + k0);
        Bs[ak + 0][arow] = b.x; Bs[ak + 1][arow] = b.y;
        Bs[ak + 2][arow] = b.z; Bs[ak + 3][arow] = b.w;
        __syncthreads();
        #pragma unroll
        for (int kk = 0; kk < 8; ++kk) {
            float ar[8], br[8];
            #pragma unroll
            for (int i = 0; i < 8; ++i) ar[i] = As[kk][ty8 + i];
            #pragma unroll
            for (int j = 0; j < 8; ++j) br[j] = Bs[kk][tx8 + j];
            #pragma unroll
            for (int i = 0; i < 8; ++i)
                #pragma unroll
                for (int j = 0; j < 8; ++j) acc[i][j] += ar[i] * br[j];
        }
        __syncthreads();
    }

    #pragma unroll
    for (int i = 0; i < 8; ++i)
        #pragma unroll
        for (int j = 0; j < 8; ++j)
            C[(size_t)(m0 + ty8 + i) * 512 + n0 + tx8 + j] = acc[i][j] * 0.015625f;
}

__global__ __launch_bounds__(256) void k_softmax()
{
    const int row  = blockIdx.x * 8 + (threadIdx.x >> 5);
    const int lane = threadIdx.x & 31;
    float* p = g_S + (size_t)row * 512;

    float v[16];
    float mx = -1e30f;
    #pragma unroll
    for (int i = 0; i < 16; ++i) { v[i] = p[lane + i * 32]; mx = fmaxf(mx, v[i]); }
    #pragma unroll
    for (int o = 16; o > 0; o >>= 1) mx = fmaxf(mx, __shfl_xor_sync(0xffffffffu, mx, o));
    float s = 0.f;
    #pragma unroll
    for (int i = 0; i < 16; ++i) { v[i] = __expf(v[i] - mx); s += v[i]; }
    #pragma unroll
    for (int o = 16; o > 0; o >>= 1) s += __shfl_xor_sync(0xffffffffu, s, o);
    const float inv = 1.f / s;
    #pragma unroll
    for (int i = 0; i < 16; ++i) p[lane + i * 32] = v[i] * inv;
}

__global__ __launch_bounds__(256) void k_pv(int dir)
{
    __shared__ float As[16][128];
    __shared__ float Bs[16][64];
    const int tid = threadIdx.x;
    const int bh = blockIdx.y;
    const int m0 = blockIdx.x * 128;

    const int k_src = dir ? 0 : 1;
    const float* __restrict__ P = g_S + (size_t)bh * 262144;
    const float* __restrict__ V = g_proj + (size_t)(k_src * 3 + 2) * NELEM_PROJ
                                  + (size_t)bh * 512 * 64;

    const int arow = tid >> 1, ak = (tid & 1) * 8;
    const int brow = tid >> 4, bn4 = (tid & 15) * 4;

    float acc[8][4];
    #pragma unroll
    for (int i = 0; i < 8; ++i)
        #pragma unroll
        for (int j = 0; j < 4; ++j) acc[i][j] = 0.f;

    const int ty8 = (tid >> 4) * 8, tx4 = (tid & 15) * 4;

    for (int k0 = 0; k0 < 512; k0 += 16) {
        float4 a0 = *(const float4*)(P + (size_t)(m0 + arow) * 512 + k0 + ak);
        float4 a1 = *(const float4*)(P + (size_t)(m0 + arow) * 512 + k0 + ak + 4);
        As[ak + 0][arow] = a0.x; As[ak + 1][arow] = a0.y;
        As[ak + 2][arow] = a0.z; As[ak + 3][arow] = a0.w;
        As[ak + 4][arow] = a1.x; As[ak + 5][arow] = a1.y;
        As[ak + 6][arow] = a1.z; As[ak + 7][arow] = a1.w;
        *(float4*)&Bs[brow][bn4] = *(const float4*)(V + (size_t)(k0 + brow) * 64 + bn4);
        __syncthreads();
        #pragma unroll
        for (int kk = 0; kk < 16; ++kk) {
            float ar[8], br[4];
            #pragma unroll
            for (int i = 0; i < 8; ++i) ar[i] = As[kk][ty8 + i];
            #pragma unroll
            for (int j = 0; j < 4; ++j) br[j] = Bs[kk][tx4 + j];
            #pragma unroll
            for (int i = 0; i < 8; ++i)
                #pragma unroll
                for (int j = 0; j < 4; ++j) acc[i][j] += ar[i] * br[j];
        }
        __syncthreads();
    }

    const int b = bh >> 4, h = bh & 15;
    float* dst = g_ctx + (size_t)dir * NELEM_PROJ;
    #pragma unroll
    for (int i = 0; i < 8; ++i) {
        const int l = m0 + ty8 + i;
        #pragma unroll
        for (int j = 0; j < 4; ++j)
            dst[(size_t)(b * 512 + l) * 1024 + h * 64 + tx4 + j] = acc[i][j];
    }
}

__global__ __launch_bounds__(256) void k_avg(float* __restrict__ out)
{
    const int e = blockIdx.x * 256 + threadIdx.x;
    const int b = e >> 18;
    const int r = e & 262143;
    float s = 0.f;
    #pragma unroll
    for (int h = 0; h < 16; ++h)
        s += g_S[(size_t)(b * 16 + h) * 262144 + r];
    out[e] = s * 0.0625f;
}

// ---------------------------------------------------------------------------
// launch
// ---------------------------------------------------------------------------
extern "C" void kernel_launch(void* const* d_in, const int* in_sizes, int n_in,
                              void* d_out, int out_size)
{
    const float* text  = (const float*)d_in[0];
    const float* image = (const float*)d_in[1];
    const float* Wq = (const float*)d_in[2];
    const float* bq = (const float*)d_in[3];
    const float* Wk = (const float*)d_in[4];
    const float* bk = (const float*)d_in[5];
    const float* Wv = (const float*)d_in[6];
    const float* bv = (const float*)d_in[7];
    const float* Wo = (const float*)d_in[8];
    const float* bo = (const float*)d_in[9];
    const float* W1 = (const float*)d_in[10];
    const float* b1 = (const float*)d_in[11];
    const float* W2 = (const float*)d_in[12];
    const float* b2 = (const float*)d_in[13];
    float* out = (float*)d_out;

    float* ctx_p = 0;
    float* hidden_p = 0;
    cudaGetSymbolAddress((void**)&ctx_p, g_ctx);
    cudaGetSymbolAddress((void**)&hidden_p, g_hidden);

    // 1) fused QKV projections (both modalities) + sigmoid, tf32 tensor cores
    k_tc<2, 1><<<dim3(24, 64), 256>>>(text, image, (const float*)0,
                                      Wq, Wk, Wv, bq, bk, bv,
                                      (float*)0, 1024, 0);

    // 2) direction 0: text queries image
    k_scores<<<dim3(4, 4, 128), 256>>>(0);
    k_softmax<<<8192, 256>>>();
    k_pv<<<dim3(4, 128), 256>>>(0);
    k_avg<<<8192, 256>>>(out + 12582912);

    // 3) direction 1: image queries text (reuses g_S)
    k_scores<<<dim3(4, 4, 128), 256>>>(1);
    k_softmax<<<8192, 256>>>();
    k_pv<<<dim3(4, 128), 256>>>(1);

    // 4) output projection: [ctx_text; ctx_image] @ Wo + bo -> d_out
    k_tc<0, 0><<<dim3(8, 64), 256>>>(ctx_p, (const float*)0, (const float*)0,
                                     Wo, Wo, Wo, bo, bo, bo,
                                     out, 1024, 0);

    // 5) FFN: hidden = relu(concat(text, image, text_cross) @ W1 + b1)
    k_tc<1, 0><<<dim3(8, 32), 256>>>(text, image, out,
                                     W1, W1, W1, b1, b1, b1,
                                     hidden_p, 3072, 1);
    //    comp_out = hidden @ W2 + b2
    k_tc<0, 0><<<dim3(8, 32), 256>>>(hidden_p, (const float*)0, (const float*)0,
                                     W2, W2, W2, b2, b2, b2,
                                     out + 8388608, 1024, 0);
}

// round 7
// speedup vs baseline: 2.6222x; 1.3853x over previous
#include <cuda_runtime.h>
#include <math.h>
#include <stdint.h>

// ---------------------------------------------------------------------------
// Problem constants
//   B=8, L=512, D=1024, H=16, DH=64
//   outputs: text_cross[4M] | image_cross[4M] | comp_out[4M] | avg_attn[2M]
// ---------------------------------------------------------------------------

#define NELEM_PROJ (4194304ul)            // B*H*L*DH

// scratch (device globals: allocation-free rule)
__device__ float g_proj[6ul * NELEM_PROJ];          // [src(2)][proj(3)][b,h,l,dh]
__device__ float g_S[128ul * 512ul * 512ul];        // [bh][q][k]  unnormalized exp (dir0)
__device__ float g_denom[128ul * 512ul];            // [bh][q] softmax denominators (dir0)
__device__ float g_ctx[2ul * NELEM_PROJ];           // [dir][b*512+l][1024]
__device__ float g_hidden[NELEM_PROJ];              // [4096][1024]

// ---------------------------------------------------------------------------
// tf32 helpers
// ---------------------------------------------------------------------------
__device__ __forceinline__ uint32_t f2tf32(float f) {
    uint32_t u;
    asm("cvt.rna.tf32.f32 %0, %1;" : "=r"(u) : "f"(f));
    return u;
}

#define MMA_TF32(d, a, b)                                                     \
    asm volatile(                                                             \
        "mma.sync.aligned.m16n8k8.row.col.f32.tf32.tf32.f32 "                 \
        "{%0,%1,%2,%3}, {%4,%5,%6,%7}, {%8,%9}, {%0,%1,%2,%3};"               \
        : "+f"(d[0]), "+f"(d[1]), "+f"(d[2]), "+f"(d[3])                      \
        : "r"(a[0]), "r"(a[1]), "r"(a[2]), "r"(a[3]), "r"(b[0]), "r"(b[1]))

// ---------------------------------------------------------------------------
// Tensor-core tf32 GEMM, BM=BN=128, BK=16, 256 threads (8 warps, 2x4),
// warp tile 32x64, mma m16n8k8.  (unchanged from passing R4 kernel)
// ---------------------------------------------------------------------------
template<int AMODE, int EMODE>
__global__ __launch_bounds__(256) void k_tc(
    const float* __restrict__ A0, const float* __restrict__ A1,
    const float* __restrict__ A2,
    const float* __restrict__ Wa, const float* __restrict__ Wb,
    const float* __restrict__ Wc,
    const float* __restrict__ ba, const float* __restrict__ bbv,
    const float* __restrict__ bc,
    float* __restrict__ C, int K, int relu)
{
    __shared__ __align__(16) uint32_t As[2][128][20];
    __shared__ __align__(16) uint32_t Bs[2][16][136];

    const int tid  = threadIdx.x;
    const int wid  = tid >> 5, lane = tid & 31;
    const int gid  = lane >> 2, tig = lane & 3;
    const int wm   = (wid & 3) * 32;
    const int wn   = (wid >> 2) * 64;

    int bsel = 0, n0;
    const float* W;
    const float* bias;
    if (AMODE == 2) {
        bsel = blockIdx.x >> 3;
        n0   = (blockIdx.x & 7) * 128;
        W    = (bsel == 0) ? Wa : (bsel == 1 ? Wb : Wc);
        bias = (bsel == 0) ? ba : (bsel == 1 ? bbv : bc);
    } else {
        n0 = blockIdx.x * 128;
        W = Wa; bias = ba;
    }
    const int m0 = blockIdx.y * 128;

    float acc[2][8][4];
    #pragma unroll
    for (int i = 0; i < 2; ++i)
        #pragma unroll
        for (int j = 0; j < 8; ++j)
            #pragma unroll
            for (int q = 0; q < 4; ++q) acc[i][j][q] = 0.f;

    float4 pa[2], pb[2];
    const int T = K >> 4;

    #pragma unroll
    for (int i = 0; i < 2; ++i) {
        const int idx = tid * 2 + i;
        const int row = idx >> 2, kc = idx & 3;
        const float* Ap;
        int col = kc * 4;
        if (AMODE == 1) { Ap = A0 + (size_t)(m0 + row) * 1024; }
        else if (AMODE == 2) {
            const int m = m0 + row;
            Ap = ((m >> 12) ? A1 : A0) + (size_t)(m & 4095) * 1024;
        } else { Ap = A0 + (size_t)(m0 + row) * 1024; }
        pa[i] = *(const float4*)(Ap + col);
        const int brow = idx >> 5, nc = idx & 31;
        pb[i] = *(const float4*)(W + (size_t)brow * 1024 + n0 + nc * 4);
    }
    #pragma unroll
    for (int i = 0; i < 2; ++i) {
        const int idx = tid * 2 + i;
        const int row = idx >> 2, kc = idx & 3;
        As[0][row][kc * 4 + 0] = f2tf32(pa[i].x);
        As[0][row][kc * 4 + 1] = f2tf32(pa[i].y);
        As[0][row][kc * 4 + 2] = f2tf32(pa[i].z);
        As[0][row][kc * 4 + 3] = f2tf32(pa[i].w);
        const int brow = idx >> 5, nc = idx & 31;
        uint4 bv;
        bv.x = f2tf32(pb[i].x); bv.y = f2tf32(pb[i].y);
        bv.z = f2tf32(pb[i].z); bv.w = f2tf32(pb[i].w);
        *(uint4*)&Bs[0][brow][nc * 4] = bv;
    }
    __syncthreads();

    for (int t = 0; t < T; ++t) {
        if (t + 1 < T) {
            const int k0 = (t + 1) * 16;
            #pragma unroll
            for (int i = 0; i < 2; ++i) {
                const int idx = tid * 2 + i;
                const int row = idx >> 2, kc = idx & 3;
                const float* Ap;
                int col = k0 + kc * 4;
                if (AMODE == 1) {
                    const int seg = k0 >> 10;
                    Ap = (seg == 0) ? A0 : (seg == 1 ? A1 : A2);
                    Ap += (size_t)(m0 + row) * 1024;
                    col = (k0 & 1023) + kc * 4;
                } else if (AMODE == 2) {
                    const int m = m0 + row;
                    Ap = ((m >> 12) ? A1 : A0) + (size_t)(m & 4095) * 1024;
                } else {
                    Ap = A0 + (size_t)(m0 + row) * 1024;
                }
                pa[i] = *(const float4*)(Ap + col);
                const int brow = idx >> 5, nc = idx & 31;
                pb[i] = *(const float4*)(W + (size_t)(k0 + brow) * 1024 + n0 + nc * 4);
            }
        }

        const int buf = t & 1;
        #pragma unroll
        for (int kk = 0; kk < 16; kk += 8) {
            uint32_t af[2][4], bf[8][2];
            #pragma unroll
            for (int tm = 0; tm < 2; ++tm) {
                const int mb = wm + tm * 16;
                af[tm][0] = As[buf][mb + gid    ][kk + tig    ];
                af[tm][1] = As[buf][mb + gid + 8][kk + tig    ];
                af[tm][2] = As[buf][mb + gid    ][kk + tig + 4];
                af[tm][3] = As[buf][mb + gid + 8][kk + tig + 4];
            }
            #pragma unroll
            for (int tn = 0; tn < 8; ++tn) {
                const int nb = wn + tn * 8;
                bf[tn][0] = Bs[buf][kk + tig    ][nb + gid];
                bf[tn][1] = Bs[buf][kk + tig + 4][nb + gid];
            }
            #pragma unroll
            for (int tm = 0; tm < 2; ++tm)
                #pragma unroll
                for (int tn = 0; tn < 8; ++tn)
                    MMA_TF32(acc[tm][tn], af[tm], bf[tn]);
        }

        if (t + 1 < T) {
            const int nbuf = (t + 1) & 1;
            #pragma unroll
            for (int i = 0; i < 2; ++i) {
                const int idx = tid * 2 + i;
                const int row = idx >> 2, kc = idx & 3;
                As[nbuf][row][kc * 4 + 0] = f2tf32(pa[i].x);
                As[nbuf][row][kc * 4 + 1] = f2tf32(pa[i].y);
                As[nbuf][row][kc * 4 + 2] = f2tf32(pa[i].z);
                As[nbuf][row][kc * 4 + 3] = f2tf32(pa[i].w);
                const int brow = idx >> 5, nc = idx & 31;
                uint4 bv;
                bv.x = f2tf32(pb[i].x); bv.y = f2tf32(pb[i].y);
                bv.z = f2tf32(pb[i].z); bv.w = f2tf32(pb[i].w);
                *(uint4*)&Bs[nbuf][brow][nc * 4] = bv;
            }
        }
        __syncthreads();
    }

    if (EMODE == 0) {
        #pragma unroll
        for (int tm = 0; tm < 2; ++tm) {
            #pragma unroll
            for (int tn = 0; tn < 8; ++tn) {
                const int r = m0 + wm + tm * 16 + gid;
                const int c = n0 + wn + tn * 8 + 2 * tig;
                float v0 = acc[tm][tn][0] + bias[c];
                float v1 = acc[tm][tn][1] + bias[c + 1];
                float v2 = acc[tm][tn][2] + bias[c];
                float v3 = acc[tm][tn][3] + bias[c + 1];
                if (relu) {
                    v0 = fmaxf(v0, 0.f); v1 = fmaxf(v1, 0.f);
                    v2 = fmaxf(v2, 0.f); v3 = fmaxf(v3, 0.f);
                }
                *(float2*)&C[(size_t)r * 1024 + c]       = make_float2(v0, v1);
                *(float2*)&C[(size_t)(r + 8) * 1024 + c] = make_float2(v2, v3);
            }
        }
    } else {
        const int src = m0 >> 12;
        float* dst = g_proj + (size_t)(src * 3 + bsel) * NELEM_PROJ;
        #pragma unroll
        for (int tm = 0; tm < 2; ++tm) {
            #pragma unroll
            for (int tn = 0; tn < 8; ++tn) {
                const int m  = m0 + wm + tm * 16 + gid;
                const int lr = m & 4095;
                const int bidx = lr >> 9;
                const int l    = lr & 511;
                const int nl = n0 + wn + tn * 8 + 2 * tig;
                const int h = nl >> 6, dh = nl & 63;
                float v0 = acc[tm][tn][0] + bias[nl];
                float v1 = acc[tm][tn][1] + bias[nl + 1];
                float v2 = acc[tm][tn][2] + bias[nl];
                float v3 = acc[tm][tn][3] + bias[nl + 1];
                if (bsel < 2) {
                    v0 = 1.f / (1.f + __expf(-v0));
                    v1 = 1.f / (1.f + __expf(-v1));
                    v2 = 1.f / (1.f + __expf(-v2));
                    v3 = 1.f / (1.f + __expf(-v3));
                }
                const size_t base0 = (size_t)((bidx * 16 + h) * 512 + l) * 64 + dh;
                const size_t base1 = (size_t)((bidx * 16 + h) * 512 + l + 8) * 64 + dh;
                *(float2*)&dst[base0] = make_float2(v0, v1);
                *(float2*)&dst[base1] = make_float2(v2, v3);
            }
        }
    }
}

// ---------------------------------------------------------------------------
// Fused flash attention (tf32 tensor cores), both directions.
//   grid (8 q-tiles, 128 bh, 2 dirs), 256 threads (8 warps: 4m x 2n).
//   Block: 64 q-rows; loops over 4 k-chunks of 128.
//   Scores in [0,1] -> softmax WITHOUT max subtraction (mathematically
//   identical, numerically safe since exp arg in [0,1]).
//   dir0 also writes unnormalized exp(S) to g_S and denominators to g_denom
//   for the avg_attn output. dir1 never touches g_S.
// Dynamic smem layout (uint32 words):
//   Qs [64][68]           @ 0      (4352)
//   KPs union             @ 4352   (8704)   Ks[128][68] / Ps[64][132]
//   Vs [128][68]          @ 13056  (8704)
//   rowsum float[64]      @ 21760  (64)
//   total 21824 words = 87296 bytes
// ---------------------------------------------------------------------------
#define ATTN_SMEM_BYTES 87296

__global__ __launch_bounds__(256) void k_attn()
{
    extern __shared__ uint32_t sm[];
    uint32_t* Qs  = sm;            // stride 68
    uint32_t* KPs = sm + 4352;     // Ks stride 68 / Ps stride 132
    uint32_t* Vs  = sm + 13056;    // stride 68
    float* rowsum = (float*)(sm + 21760);

    const int tid = threadIdx.x;
    const int wid = tid >> 5, lane = tid & 31;
    const int gid = lane >> 2, tig = lane & 3;
    const int wm  = (wid & 3) * 16;       // warp q-row base (0..48)
    const int wns = (wid >> 2) * 64;      // S-gemm n base (0/64)
    const int wno = (wid >> 2) * 32;      // O-gemm n base (0/32)

    const int qt = blockIdx.x, bh = blockIdx.y, dir = blockIdx.z;
    const int q0 = qt * 64;

    const int q_src = dir ? 1 : 0, k_src = dir ? 0 : 1;
    const float* __restrict__ Qg = g_proj + (size_t)(q_src * 3 + 0) * NELEM_PROJ
                                   + (size_t)bh * 512 * 64;
    const float* __restrict__ Kg = g_proj + (size_t)(k_src * 3 + 1) * NELEM_PROJ
                                   + (size_t)bh * 512 * 64;
    const float* __restrict__ Vg = g_proj + (size_t)(k_src * 3 + 2) * NELEM_PROJ
                                   + (size_t)bh * 512 * 64;

    if (tid < 64) rowsum[tid] = 0.f;

    // load Q tile [64][64] -> Qs (tf32)
    #pragma unroll
    for (int i = 0; i < 4; ++i) {
        const int f = tid + i * 256;            // 1024 float4
        const int row = f >> 4, c4 = (f & 15) * 4;
        float4 v = *(const float4*)(Qg + (size_t)(q0 + row) * 64 + c4);
        Qs[row * 68 + c4 + 0] = f2tf32(v.x);
        Qs[row * 68 + c4 + 1] = f2tf32(v.y);
        Qs[row * 68 + c4 + 2] = f2tf32(v.z);
        Qs[row * 68 + c4 + 3] = f2tf32(v.w);
    }

    float accO[4][4];
    #pragma unroll
    for (int tn = 0; tn < 4; ++tn)
        #pragma unroll
        for (int q = 0; q < 4; ++q) accO[tn][q] = 0.f;
    float sum0 = 0.f, sum1 = 0.f;

    for (int kc = 0; kc < 4; ++kc) {
        const int s0 = kc * 128;

        // load K, V chunks [128][64] -> tf32 smem (coalesced, conflict-free)
        #pragma unroll
        for (int i = 0; i < 8; ++i) {
            const int f = tid + i * 256;        // 2048 float4
            const int row = f >> 4, c4 = (f & 15) * 4;
            float4 kv = *(const float4*)(Kg + (size_t)(s0 + row) * 64 + c4);
            KPs[row * 68 + c4 + 0] = f2tf32(kv.x);
            KPs[row * 68 + c4 + 1] = f2tf32(kv.y);
            KPs[row * 68 + c4 + 2] = f2tf32(kv.z);
            KPs[row * 68 + c4 + 3] = f2tf32(kv.w);
            float4 vv = *(const float4*)(Vg + (size_t)(s0 + row) * 64 + c4);
            Vs[row * 68 + c4 + 0] = f2tf32(vv.x);
            Vs[row * 68 + c4 + 1] = f2tf32(vv.y);
            Vs[row * 68 + c4 + 2] = f2tf32(vv.z);
            Vs[row * 68 + c4 + 3] = f2tf32(vv.w);
        }
        __syncthreads();

        // S = muQ @ muK^T  (M=64, N=128, K=64); warp tile 16x64
        float accS[8][4];
        #pragma unroll
        for (int tn = 0; tn < 8; ++tn)
            #pragma unroll
            for (int q = 0; q < 4; ++q) accS[tn][q] = 0.f;

        #pragma unroll
        for (int kk = 0; kk < 64; kk += 8) {
            uint32_t af[4];
            af[0] = Qs[(wm + gid    ) * 68 + kk + tig    ];
            af[1] = Qs[(wm + gid + 8) * 68 + kk + tig    ];
            af[2] = Qs[(wm + gid    ) * 68 + kk + tig + 4];
            af[3] = Qs[(wm + gid + 8) * 68 + kk + tig + 4];
            #pragma unroll
            for (int tn = 0; tn < 8; ++tn) {
                const int nb = wns + tn * 8;
                uint32_t bf[2];
                bf[0] = KPs[(nb + gid) * 68 + kk + tig    ];
                bf[1] = KPs[(nb + gid) * 68 + kk + tig + 4];
                MMA_TF32(accS[tn], af, bf);
            }
        }
        __syncthreads();     // all warps done reading Ks before Ps overwrites

        // exp (no max-sub needed), stage P (tf32) into KPs, rowsum, dir0 spill
        #pragma unroll
        for (int tn = 0; tn < 8; ++tn) {
            const float p0 = __expf(accS[tn][0] * 0.015625f);
            const float p1 = __expf(accS[tn][1] * 0.015625f);
            const float p2 = __expf(accS[tn][2] * 0.015625f);
            const float p3 = __expf(accS[tn][3] * 0.015625f);
            sum0 += p0 + p1;
            sum1 += p2 + p3;
            const int c  = wns + tn * 8 + 2 * tig;
            const int r0 = wm + gid, r1 = wm + gid + 8;
            uint2 u0; u0.x = f2tf32(p0); u0.y = f2tf32(p1);
            uint2 u1; u1.x = f2tf32(p2); u1.y = f2tf32(p3);
            *(uint2*)&KPs[r0 * 132 + c] = u0;
            *(uint2*)&KPs[r1 * 132 + c] = u1;
            if (dir == 0) {
                float* Sg = g_S + (size_t)bh * 262144;
                *(float2*)&Sg[(size_t)(q0 + r0) * 512 + s0 + c] = make_float2(p0, p1);
                *(float2*)&Sg[(size_t)(q0 + r1) * 512 + s0 + c] = make_float2(p2, p3);
            }
        }
        __syncthreads();

        // O += P @ V  (M=64, N=64, K=128); warp tile 16x32
        #pragma unroll
        for (int kk = 0; kk < 128; kk += 8) {
            uint32_t af[4];
            af[0] = KPs[(wm + gid    ) * 132 + kk + tig    ];
            af[1] = KPs[(wm + gid + 8) * 132 + kk + tig    ];
            af[2] = KPs[(wm + gid    ) * 132 + kk + tig + 4];
            af[3] = KPs[(wm + gid + 8) * 132 + kk + tig + 4];
            #pragma unroll
            for (int tn = 0; tn < 4; ++tn) {
                const int nb = wno + tn * 8;
                uint32_t bf[2];
                bf[0] = Vs[(kk + tig    ) * 68 + nb + gid];
                bf[1] = Vs[(kk + tig + 4) * 68 + nb + gid];
                MMA_TF32(accO[tn], af, bf);
            }
        }
        __syncthreads();     // before next chunk overwrites Ks/Ps and Vs
    }

    // row-sum reduction: quad (tig) via shuffle, then 2 n-warps via smem atomics
    sum0 += __shfl_xor_sync(0xffffffffu, sum0, 1);
    sum0 += __shfl_xor_sync(0xffffffffu, sum0, 2);
    sum1 += __shfl_xor_sync(0xffffffffu, sum1, 1);
    sum1 += __shfl_xor_sync(0xffffffffu, sum1, 2);
    if (tig == 0) {
        atomicAdd(&rowsum[wm + gid    ], sum0);
        atomicAdd(&rowsum[wm + gid + 8], sum1);
    }
    __syncthreads();

    // normalize and scatter O to g_ctx[dir][(b*512+l)*1024 + h*64 + dh]
    const int b = bh >> 4, h = bh & 15;
    float* dst = g_ctx + (size_t)dir * NELEM_PROJ;
    const float inv0 = 1.f / rowsum[wm + gid];
    const float inv1 = 1.f / rowsum[wm + gid + 8];
    #pragma unroll
    for (int tn = 0; tn < 4; ++tn) {
        const int dh = wno + tn * 8 + 2 * tig;
        const int l0 = q0 + wm + gid, l1 = l0 + 8;
        *(float2*)&dst[(size_t)(b * 512 + l0) * 1024 + h * 64 + dh] =
            make_float2(accO[tn][0] * inv0, accO[tn][1] * inv0);
        *(float2*)&dst[(size_t)(b * 512 + l1) * 1024 + h * 64 + dh] =
            make_float2(accO[tn][2] * inv1, accO[tn][3] * inv1);
    }

    if (dir == 0 && tid < 64)
        g_denom[(size_t)bh * 512 + q0 + tid] = rowsum[tid];
}

// ---------------------------------------------------------------------------
// avg_attn[b][q][k] = (1/16) sum_h expS[bh][q][k] / denom[bh][q]
// ---------------------------------------------------------------------------
__global__ __launch_bounds__(256) void k_avg(float* __restrict__ out)
{
    const int e = blockIdx.x * 256 + threadIdx.x;    // 2,097,152
    const int b = e >> 18;
    const int r = e & 262143;
    const int q = r >> 9;
    float s = 0.f;
    #pragma unroll
    for (int h = 0; h < 16; ++h) {
        const float d = g_denom[(size_t)(b * 16 + h) * 512 + q];
        s += g_S[(size_t)(b * 16 + h) * 262144 + r] * __frcp_rn(d);
    }
    out[e] = s * 0.0625f;
}

// ---------------------------------------------------------------------------
// launch
// ---------------------------------------------------------------------------
extern "C" void kernel_launch(void* const* d_in, const int* in_sizes, int n_in,
                              void* d_out, int out_size)
{
    const float* text  = (const float*)d_in[0];
    const float* image = (const float*)d_in[1];
    const float* Wq = (const float*)d_in[2];
    const float* bq = (const float*)d_in[3];
    const float* Wk = (const float*)d_in[4];
    const float* bk = (const float*)d_in[5];
    const float* Wv = (const float*)d_in[6];
    const float* bv = (const float*)d_in[7];
    const float* Wo = (const float*)d_in[8];
    const float* bo = (const float*)d_in[9];
    const float* W1 = (const float*)d_in[10];
    const float* b1 = (const float*)d_in[11];
    const float* W2 = (const float*)d_in[12];
    const float* b2 = (const float*)d_in[13];
    float* out = (float*)d_out;

    float* ctx_p = 0;
    float* hidden_p = 0;
    cudaGetSymbolAddress((void**)&ctx_p, g_ctx);
    cudaGetSymbolAddress((void**)&hidden_p, g_hidden);

    cudaFuncSetAttribute(k_attn, cudaFuncAttributeMaxDynamicSharedMemorySize,
                         ATTN_SMEM_BYTES);

    // 1) fused QKV projections (both modalities) + sigmoid, tf32 tensor cores
    k_tc<2, 1><<<dim3(24, 64), 256>>>(text, image, (const float*)0,
                                      Wq, Wk, Wv, bq, bk, bv,
                                      (float*)0, 1024, 0);

    // 2) fused flash attention, both directions in one launch
    k_attn<<<dim3(8, 128, 2), 256, ATTN_SMEM_BYTES>>>();

    // 3) avg_attn from dir-0 unnormalized probs + denominators
    k_avg<<<8192, 256>>>(out + 12582912);

    // 4) output projection: [ctx_text; ctx_image] @ Wo + bo -> d_out
    k_tc<0, 0><<<dim3(8, 64), 256>>>(ctx_p, (const float*)0, (const float*)0,
                                     Wo, Wo, Wo, bo, bo, bo,
                                     out, 1024, 0);

    // 5) FFN: hidden = relu(concat(text, image, text_cross) @ W1 + b1)
    k_tc<1, 0><<<dim3(8, 32), 256>>>(text, image, out,
                                     W1, W1, W1, b1, b1, b1,
                                     hidden_p, 3072, 1);
    //    comp_out = hidden @ W2 + b2
    k_tc<0, 0><<<dim3(8, 32), 256>>>(hidden_p, (const float*)0, (const float*)0,
                                     W2, W2, W2, b2, b2, b2,
                                     out + 8388608, 1024, 0);
}

// round 9
// speedup vs baseline: 3.2319x; 1.2325x over previous
#include <cuda_runtime.h>
#include <math.h>
#include <stdint.h>

// ---------------------------------------------------------------------------
// Problem constants
//   B=8, L=512, D=1024, H=16, DH=64
//   outputs: text_cross[4M] | image_cross[4M] | comp_out[4M] | avg_attn[2M]
// ---------------------------------------------------------------------------

#define NELEM_PROJ (4194304ul)            // B*H*L*DH
#define MW (1048576ul)                    // 1024*1024

// scratch (device globals: allocation-free rule). tf32 payloads as uint32.
__device__ uint32_t g_xin_tf[8ul * MW / 1024ul * 1024ul]; // [text(4096) ; image(4096)][1024]
__device__ uint32_t g_w_tf[8ul * MW];               // Wq|Wk|Wv|Wo|W1(3M)|W2
__device__ uint32_t g_proj[6ul * NELEM_PROJ];       // [src(2)][proj(3)][b,h,l,dh] tf32
__device__ float    g_S[128ul * 512ul * 512ul];     // [bh][q][k] unnormalized exp (dir0)
__device__ float    g_denom[128ul * 512ul];         // [bh][q] softmax denominators (dir0)
__device__ uint32_t g_ctx_tf[2ul * NELEM_PROJ];     // [dir][b*512+l][1024] tf32
__device__ uint32_t g_tc_tf[NELEM_PROJ];            // text_cross tf32 [4096][1024]
__device__ uint32_t g_hidden_tf[NELEM_PROJ];        // [4096][1024] tf32

// ---------------------------------------------------------------------------
// helpers
// ---------------------------------------------------------------------------
__device__ __forceinline__ uint32_t f2tf32(float f) {
    uint32_t u;
    asm("cvt.rna.tf32.f32 %0, %1;" : "=r"(u) : "f"(f));
    return u;
}

__device__ __forceinline__ uint32_t sptr(const void* p) {
    return (uint32_t)__cvta_generic_to_shared(p);
}

__device__ __forceinline__ void cp16(uint32_t s, const void* g) {
    asm volatile("cp.async.cg.shared.global [%0], [%1], 16;" :: "r"(s), "l"(g));
}
#define CP_COMMIT() asm volatile("cp.async.commit_group;")
#define CP_WAIT1()  asm volatile("cp.async.wait_group 1;" ::: "memory")

#define MMA_TF32(d, a, b)                                                     \
    asm volatile(                                                             \
        "mma.sync.aligned.m16n8k8.row.col.f32.tf32.tf32.f32 "                 \
        "{%0,%1,%2,%3}, {%4,%5,%6,%7}, {%8,%9}, {%0,%1,%2,%3};"               \
        : "+f"(d[0]), "+f"(d[1]), "+f"(d[2]), "+f"(d[3])                      \
        : "r"(a[0]), "r"(a[1]), "r"(a[2]), "r"(a[3]), "r"(b[0]), "r"(b[1]))

// ---------------------------------------------------------------------------
// k_cvt: fp32 -> tf32 (rna), vectorized by 4.
// ---------------------------------------------------------------------------
__global__ __launch_bounds__(256) void k_cvt(
    const float* __restrict__ src, uint32_t* __restrict__ dst, int n4)
{
    const int i = blockIdx.x * 256 + threadIdx.x;
    if (i < n4) {
        float4 v = ((const float4*)src)[i];
        uint4 u;
        u.x = f2tf32(v.x); u.y = f2tf32(v.y);
        u.z = f2tf32(v.z); u.w = f2tf32(v.w);
        ((uint4*)dst)[i] = u;
    }
}

// ---------------------------------------------------------------------------
// Tensor-core tf32 GEMM, BM=BN=128, BK=16, 256 threads (8 warps, 4m x 2n),
// warp tile 32x64, mma m16n8k8. A and W already tf32 in global (uint32).
// 3-stage cp.async pipeline.
//   AMODE 0: A = A0[M][1024]
//   AMODE 1: K=3072 concat: k<1024 -> A0, <2048 -> A1, else A2 (each [M][1024])
//   EMODE 0: C fp32 = acc + bias                  (W2, final)
//   EMODE 1: proj: sigmoid for bsel<2, scatter tf32 into g_proj head layout
//   EMODE 2: Wo: C fp32 = acc + bias, and tf32 copy to g_tc_tf for m0<4096
//   EMODE 3: FFN1: relu, tf32 only to g_hidden_tf
// EMODE1: grid.x=24, bsel=x>>3 picks W at Wbase + bsel*1M and bias.
// Dynamic smem: As[3][128][20] + Bs[3][16][136] = 56832 bytes.
// ---------------------------------------------------------------------------
#define TC_SMEM_BYTES 56832

template<int AMODE, int EMODE>
__global__ __launch_bounds__(256) void k_tc2(
    const uint32_t* __restrict__ A0, const uint32_t* __restrict__ A1,
    const uint32_t* __restrict__ A2, const uint32_t* __restrict__ Wbase,
    const float* __restrict__ ba, const float* __restrict__ bb,
    const float* __restrict__ bc,
    float* __restrict__ C, int K)
{
    extern __shared__ uint32_t smem_tc[];
    uint32_t (*As)[128][20] = (uint32_t(*)[128][20])smem_tc;
    uint32_t (*Bs)[16][136] = (uint32_t(*)[16][136])(smem_tc + 3 * 128 * 20);

    const int tid  = threadIdx.x;
    const int wid  = tid >> 5, lane = tid & 31;
    const int gid  = lane >> 2, tig = lane & 3;
    const int wm   = (wid & 3) * 32;
    const int wn   = (wid >> 2) * 64;

    int bsel = 0, n0;
    const uint32_t* W;
    const float* bias;
    if (EMODE == 1) {
        bsel = blockIdx.x >> 3;
        n0   = (blockIdx.x & 7) * 128;
        W    = Wbase + (size_t)bsel * MW;
        bias = (bsel == 0) ? ba : (bsel == 1 ? bb : bc);
    } else {
        n0 = blockIdx.x * 128;
        W = Wbase; bias = ba;
    }
    const int m0 = blockIdx.y * 128;

    float acc[2][8][4];
    #pragma unroll
    for (int i = 0; i < 2; ++i)
        #pragma unroll
        for (int j = 0; j < 8; ++j)
            #pragma unroll
            for (int q = 0; q < 4; ++q) acc[i][j][q] = 0.f;

    const int T = K >> 4;

    // loader lambda: stage st, k-offset k0
    auto load_stage = [&](int st, int k0) {
        #pragma unroll
        for (int i = 0; i < 2; ++i) {
            const int c = tid + i * 256;          // 0..511
            const int arow = c >> 2, akc = c & 3;
            const uint32_t* ga;
            if (AMODE == 1) {
                const int seg = k0 >> 10;
                const uint32_t* base = (seg == 0) ? A0 : (seg == 1 ? A1 : A2);
                ga = base + (size_t)(m0 + arow) * 1024 + (k0 & 1023) + akc * 4;
            } else {
                ga = A0 + (size_t)(m0 + arow) * 1024 + k0 + akc * 4;
            }
            cp16(sptr(&As[st][arow][akc * 4]), ga);
            const int bkr = c >> 5, bnc = c & 31;
            cp16(sptr(&Bs[st][bkr][bnc * 4]),
                 W + (size_t)(k0 + bkr) * 1024 + n0 + bnc * 4);
        }
    };

    // prologue: stages 0, 1
    load_stage(0, 0);  CP_COMMIT();
    load_stage(1, 16); CP_COMMIT();

    for (int t = 0; t < T; ++t) {
        CP_WAIT1();
        __syncthreads();

        // issue next stage before compute (deeper latency cover)
        if (t + 2 < T) load_stage((t + 2) % 3, (t + 2) * 16);
        CP_COMMIT();

        const int buf = t % 3;
        #pragma unroll
        for (int kk = 0; kk < 16; kk += 8) {
            uint32_t af[2][4], bf[8][2];
            #pragma unroll
            for (int tm = 0; tm < 2; ++tm) {
                const int mb = wm + tm * 16;
                af[tm][0] = As[buf][mb + gid    ][kk + tig    ];
                af[tm][1] = As[buf][mb + gid + 8][kk + tig    ];
                af[tm][2] = As[buf][mb + gid    ][kk + tig + 4];
                af[tm][3] = As[buf][mb + gid + 8][kk + tig + 4];
            }
            #pragma unroll
            for (int tn = 0; tn < 8; ++tn) {
                const int nb = wn + tn * 8;
                bf[tn][0] = Bs[buf][kk + tig    ][nb + gid];
                bf[tn][1] = Bs[buf][kk + tig + 4][nb + gid];
            }
            #pragma unroll
            for (int tm = 0; tm < 2; ++tm)
                #pragma unroll
                for (int tn = 0; tn < 8; ++tn)
                    MMA_TF32(acc[tm][tn], af[tm], bf[tn]);
        }
        __syncthreads();
    }

    // ---- epilogue ----
    if (EMODE == 0 || EMODE == 2) {
        #pragma unroll
        for (int tm = 0; tm < 2; ++tm) {
            #pragma unroll
            for (int tn = 0; tn < 8; ++tn) {
                const int r = m0 + wm + tm * 16 + gid;
                const int c = n0 + wn + tn * 8 + 2 * tig;
                float v0 = acc[tm][tn][0] + bias[c];
                float v1 = acc[tm][tn][1] + bias[c + 1];
                float v2 = acc[tm][tn][2] + bias[c];
                float v3 = acc[tm][tn][3] + bias[c + 1];
                *(float2*)&C[(size_t)r * 1024 + c]       = make_float2(v0, v1);
                *(float2*)&C[(size_t)(r + 8) * 1024 + c] = make_float2(v2, v3);
                if (EMODE == 2 && m0 < 4096) {
                    uint2 u0; u0.x = f2tf32(v0); u0.y = f2tf32(v1);
                    uint2 u1; u1.x = f2tf32(v2); u1.y = f2tf32(v3);
                    *(uint2*)&g_tc_tf[(size_t)r * 1024 + c]       = u0;
                    *(uint2*)&g_tc_tf[(size_t)(r + 8) * 1024 + c] = u1;
                }
            }
        }
    } else if (EMODE == 3) {
        #pragma unroll
        for (int tm = 0; tm < 2; ++tm) {
            #pragma unroll
            for (int tn = 0; tn < 8; ++tn) {
                const int r = m0 + wm + tm * 16 + gid;
                const int c = n0 + wn + tn * 8 + 2 * tig;
                uint2 u0, u1;
                u0.x = f2tf32(fmaxf(acc[tm][tn][0] + bias[c],     0.f));
                u0.y = f2tf32(fmaxf(acc[tm][tn][1] + bias[c + 1], 0.f));
                u1.x = f2tf32(fmaxf(acc[tm][tn][2] + bias[c],     0.f));
                u1.y = f2tf32(fmaxf(acc[tm][tn][3] + bias[c + 1], 0.f));
                *(uint2*)&g_hidden_tf[(size_t)r * 1024 + c]       = u0;
                *(uint2*)&g_hidden_tf[(size_t)(r + 8) * 1024 + c] = u1;
            }
        }
    } else {  // EMODE 1: proj
        const int src = m0 >> 12;
        uint32_t* dst = g_proj + (size_t)(src * 3 + bsel) * NELEM_PROJ;
        #pragma unroll
        for (int tm = 0; tm < 2; ++tm) {
            #pragma unroll
            for (int tn = 0; tn < 8; ++tn) {
                const int m  = m0 + wm + tm * 16 + gid;
                const int lr = m & 4095;
                const int bidx = lr >> 9;
                const int l    = lr & 511;
                const int nl = n0 + wn + tn * 8 + 2 * tig;
                const int h = nl >> 6, dh = nl & 63;
                float v0 = acc[tm][tn][0] + bias[nl];
                float v1 = acc[tm][tn][1] + bias[nl + 1];
                float v2 = acc[tm][tn][2] + bias[nl];
                float v3 = acc[tm][tn][3] + bias[nl + 1];
                if (bsel < 2) {
                    v0 = 1.f / (1.f + __expf(-v0));
                    v1 = 1.f / (1.f + __expf(-v1));
                    v2 = 1.f / (1.f + __expf(-v2));
                    v3 = 1.f / (1.f + __expf(-v3));
                }
                uint2 u0; u0.x = f2tf32(v0); u0.y = f2tf32(v1);
                uint2 u1; u1.x = f2tf32(v2); u1.y = f2tf32(v3);
                const size_t base0 = (size_t)((bidx * 16 + h) * 512 + l) * 64 + dh;
                const size_t base1 = (size_t)((bidx * 16 + h) * 512 + l + 8) * 64 + dh;
                *(uint2*)&dst[base0] = u0;
                *(uint2*)&dst[base1] = u1;
            }
        }
    }
}

// ---------------------------------------------------------------------------
// Fused flash attention (tf32 tensor cores), both directions.
//   grid (8 q-tiles, 128 bh, 2 dirs), 256 threads (8 warps: 4m x 2n).
//   g_proj already tf32 -> plain uint4 copies into smem.
//   Scores in [0,1] -> softmax without max subtraction.
//   dir0 writes unnormalized exp(S) to g_S + denominators to g_denom.
//   Output ctx written as tf32 into g_ctx_tf.
// smem words: Qs[64][68]=4352 | KPs 8704 (Ks[128][68] / Ps[64][132]) |
//             Vs[128][68]=8704 | rowsum 64  -> 21824 words = 87296 B
// ---------------------------------------------------------------------------
#define ATTN_SMEM_BYTES 87296

__global__ __launch_bounds__(256) void k_attn()
{
    extern __shared__ uint32_t sm[];
    uint32_t* Qs  = sm;            // stride 68
    uint32_t* KPs = sm + 4352;     // Ks stride 68 / Ps stride 132
    uint32_t* Vs  = sm + 13056;    // stride 68
    float* rowsum = (float*)(sm + 21760);

    const int tid = threadIdx.x;
    const int wid = tid >> 5, lane = tid & 31;
    const int gid = lane >> 2, tig = lane & 3;
    const int wm  = (wid & 3) * 16;
    const int wns = (wid >> 2) * 64;
    const int wno = (wid >> 2) * 32;

    const int qt = blockIdx.x, bh = blockIdx.y, dir = blockIdx.z;
    const int q0 = qt * 64;

    const int q_src = dir ? 1 : 0, k_src = dir ? 0 : 1;
    const uint32_t* __restrict__ Qg = g_proj + (size_t)(q_src * 3 + 0) * NELEM_PROJ
                                      + (size_t)bh * 512 * 64;
    const uint32_t* __restrict__ Kg = g_proj + (size_t)(k_src * 3 + 1) * NELEM_PROJ
                                      + (size_t)bh * 512 * 64;
    const uint32_t* __restrict__ Vg = g_proj + (size_t)(k_src * 3 + 2) * NELEM_PROJ
                                      + (size_t)bh * 512 * 64;

    if (tid < 64) rowsum[tid] = 0.f;

    #pragma unroll
    for (int i = 0; i < 4; ++i) {
        const int f = tid + i * 256;
        const int row = f >> 4, c4 = (f & 15) * 4;
        *(uint4*)&Qs[row * 68 + c4] = *(const uint4*)(Qg + (size_t)(q0 + row) * 64 + c4);
    }

    float accO[4][4];
    #pragma unroll
    for (int tn = 0; tn < 4; ++tn)
        #pragma unroll
        for (int q = 0; q < 4; ++q) accO[tn][q] = 0.f;
    float sum0 = 0.f, sum1 = 0.f;

    for (int kc = 0; kc < 4; ++kc) {
        const int s0 = kc * 128;

        #pragma unroll
        for (int i = 0; i < 8; ++i) {
            const int f = tid + i * 256;
            const int row = f >> 4, c4 = (f & 15) * 4;
            *(uint4*)&KPs[row * 68 + c4] =
                *(const uint4*)(Kg + (size_t)(s0 + row) * 64 + c4);
            *(uint4*)&Vs[row * 68 + c4] =
                *(const uint4*)(Vg + (size_t)(s0 + row) * 64 + c4);
        }
        __syncthreads();

        float accS[8][4];
        #pragma unroll
        for (int tn = 0; tn < 8; ++tn)
            #pragma unroll
            for (int q = 0; q < 4; ++q) accS[tn][q] = 0.f;

        #pragma unroll
        for (int kk = 0; kk < 64; kk += 8) {
            uint32_t af[4];
            af[0] = Qs[(wm + gid    ) * 68 + kk + tig    ];
            af[1] = Qs[(wm + gid + 8) * 68 + kk + tig    ];
            af[2] = Qs[(wm + gid    ) * 68 + kk + tig + 4];
            af[3] = Qs[(wm + gid + 8) * 68 + kk + tig + 4];
            #pragma unroll
            for (int tn = 0; tn < 8; ++tn) {
                const int nb = wns + tn * 8;
                uint32_t bf[2];
                bf[0] = KPs[(nb + gid) * 68 + kk + tig    ];
                bf[1] = KPs[(nb + gid) * 68 + kk + tig + 4];
                MMA_TF32(accS[tn], af, bf);
            }
        }
        __syncthreads();

        #pragma unroll
        for (int tn = 0; tn < 8; ++tn) {
            const float p0 = __expf(accS[tn][0] * 0.015625f);
            const float p1 = __expf(accS[tn][1] * 0.015625f);
            const float p2 = __expf(accS[tn][2] * 0.015625f);
            const float p3 = __expf(accS[tn][3] * 0.015625f);
            sum0 += p0 + p1;
            sum1 += p2 + p3;
            const int c  = wns + tn * 8 + 2 * tig;
            const int r0 = wm + gid, r1 = wm + gid + 8;
            uint2 u0; u0.x = f2tf32(p0); u0.y = f2tf32(p1);
            uint2 u1; u1.x = f2tf32(p2); u1.y = f2tf32(p3);
            *(uint2*)&KPs[r0 * 132 + c] = u0;
            *(uint2*)&KPs[r1 * 132 + c] = u1;
            if (dir == 0) {
                float* Sg = g_S + (size_t)bh * 262144;
                *(float2*)&Sg[(size_t)(q0 + r0) * 512 + s0 + c] = make_float2(p0, p1);
                *(float2*)&Sg[(size_t)(q0 + r1) * 512 + s0 + c] = make_float2(p2, p3);
            }
        }
        __syncthreads();

        #pragma unroll
        for (int kk = 0; kk < 128; kk += 8) {
            uint32_t af[4];
            af[0] = KPs[(wm + gid    ) * 132 + kk + tig    ];
            af[1] = KPs[(wm + gid + 8) * 132 + kk + tig    ];
            af[2] = KPs[(wm + gid    ) * 132 + kk + tig + 4];
            af[3] = KPs[(wm + gid + 8) * 132 + kk + tig + 4];
            #pragma unroll
            for (int tn = 0; tn < 4; ++tn) {
                const int nb = wno + tn * 8;
                uint32_t bf[2];
                bf[0] = Vs[(kk + tig    ) * 68 + nb + gid];
                bf[1] = Vs[(kk + tig + 4) * 68 + nb + gid];
                MMA_TF32(accO[tn], af, bf);
            }
        }
        __syncthreads();
    }

    sum0 += __shfl_xor_sync(0xffffffffu, sum0, 1);
    sum0 += __shfl_xor_sync(0xffffffffu, sum0, 2);
    sum1 += __shfl_xor_sync(0xffffffffu, sum1, 1);
    sum1 += __shfl_xor_sync(0xffffffffu, sum1, 2);
    if (tig == 0) {
        atomicAdd(&rowsum[wm + gid    ], sum0);
        atomicAdd(&rowsum[wm + gid + 8], sum1);
    }
    __syncthreads();

    const int b = bh >> 4, h = bh & 15;
    uint32_t* dst = g_ctx_tf + (size_t)dir * NELEM_PROJ;
    const float inv0 = 1.f / rowsum[wm + gid];
    const float inv1 = 1.f / rowsum[wm + gid + 8];
    #pragma unroll
    for (int tn = 0; tn < 4; ++tn) {
        const int dh = wno + tn * 8 + 2 * tig;
        const int l0 = q0 + wm + gid, l1 = l0 + 8;
        uint2 u0, u1;
        u0.x = f2tf32(accO[tn][0] * inv0); u0.y = f2tf32(accO[tn][1] * inv0);
        u1.x = f2tf32(accO[tn][2] * inv1); u1.y = f2tf32(accO[tn][3] * inv1);
        *(uint2*)&dst[(size_t)(b * 512 + l0) * 1024 + h * 64 + dh] = u0;
        *(uint2*)&dst[(size_t)(b * 512 + l1) * 1024 + h * 64 + dh] = u1;
    }

    if (dir == 0 && tid < 64)
        g_denom[(size_t)bh * 512 + q0 + tid] = rowsum[tid];
}

// ---------------------------------------------------------------------------
// avg_attn[b][q][k] = (1/16) sum_h expS[bh][q][k] / denom[bh][q]
// ---------------------------------------------------------------------------
__global__ __launch_bounds__(256) void k_avg(float* __restrict__ out)
{
    const int e = blockIdx.x * 256 + threadIdx.x;
    const int b = e >> 18;
    const int r = e & 262143;
    const int q = r >> 9;
    float s = 0.f;
    #pragma unroll
    for (int h = 0; h < 16; ++h) {
        const float d = g_denom[(size_t)(b * 16 + h) * 512 + q];
        s += g_S[(size_t)(b * 16 + h) * 262144 + r] * __frcp_rn(d);
    }
    out[e] = s * 0.0625f;
}

// ---------------------------------------------------------------------------
// launch
// ---------------------------------------------------------------------------
extern "C" void kernel_launch(void* const* d_in, const int* in_sizes, int n_in,
                              void* d_out, int out_size)
{
    const float* text  = (const float*)d_in[0];
    const float* image = (const float*)d_in[1];
    const float* Wq = (const float*)d_in[2];
    const float* bq = (const float*)d_in[3];
    const float* Wk = (const float*)d_in[4];
    const float* bk = (const float*)d_in[5];
    const float* Wv = (const float*)d_in[6];
    const float* bv = (const float*)d_in[7];
    const float* Wo = (const float*)d_in[8];
    const float* bo = (const float*)d_in[9];
    const float* W1 = (const float*)d_in[10];
    const float* b1 = (const float*)d_in[11];
    const float* W2 = (const float*)d_in[12];
    const float* b2 = (const float*)d_in[13];
    float* out = (float*)d_out;

    uint32_t *xin_p = 0, *w_p = 0, *ctx_p = 0, *tc_p = 0, *hid_p = 0;
    cudaGetSymbolAddress((void**)&xin_p, g_xin_tf);
    cudaGetSymbolAddress((void**)&w_p,   g_w_tf);
    cudaGetSymbolAddress((void**)&ctx_p, g_ctx_tf);
    cudaGetSymbolAddress((void**)&tc_p,  g_tc_tf);
    cudaGetSymbolAddress((void**)&hid_p, g_hidden_tf);

    cudaFuncSetAttribute(k_attn, cudaFuncAttributeMaxDynamicSharedMemorySize,
                         ATTN_SMEM_BYTES);
    cudaFuncSetAttribute(k_tc2<0, 1>, cudaFuncAttributeMaxDynamicSharedMemorySize,
                         TC_SMEM_BYTES);
    cudaFuncSetAttribute(k_tc2<0, 2>, cudaFuncAttributeMaxDynamicSharedMemorySize,
                         TC_SMEM_BYTES);
    cudaFuncSetAttribute(k_tc2<1, 3>, cudaFuncAttributeMaxDynamicSharedMemorySize,
                         TC_SMEM_BYTES);
    cudaFuncSetAttribute(k_tc2<0, 0>, cudaFuncAttributeMaxDynamicSharedMemorySize,
                         TC_SMEM_BYTES);

    // 0) convert inputs + weights to tf32 once
    k_cvt<<<4096, 256>>>(text,  xin_p,               1048576);
    k_cvt<<<4096, 256>>>(image, xin_p + 4096ul * 1024ul, 1048576);
    k_cvt<<<1024, 256>>>(Wq, w_p,           262144);
    k_cvt<<<1024, 256>>>(Wk, w_p + 1ul * MW, 262144);
    k_cvt<<<1024, 256>>>(Wv, w_p + 2ul * MW, 262144);
    k_cvt<<<1024, 256>>>(Wo, w_p + 3ul * MW, 262144);
    k_cvt<<<3072, 256>>>(W1, w_p + 4ul * MW, 786432);
    k_cvt<<<1024, 256>>>(W2, w_p + 7ul * MW, 262144);

    // 1) fused QKV projections (both modalities) + sigmoid -> g_proj (tf32)
    k_tc2<0, 1><<<dim3(24, 64), 256, TC_SMEM_BYTES>>>(
        xin_p, (const uint32_t*)0, (const uint32_t*)0, w_p,
        bq, bk, bv, (float*)0, 1024);

    // 2) fused flash attention, both directions
    k_attn<<<dim3(8, 128, 2), 256, ATTN_SMEM_BYTES>>>();

    // 3) avg_attn from dir-0 unnormalized probs + denominators
    k_avg<<<8192, 256>>>(out + 12582912);

    // 4) output projection -> d_out (fp32) + text_cross tf32 copy
    k_tc2<0, 2><<<dim3(8, 64), 256, TC_SMEM_BYTES>>>(
        ctx_p, (const uint32_t*)0, (const uint32_t*)0, w_p + 3ul * MW,
        bo, bo, bo, out, 1024);

    // 5) FFN1: hidden = relu(concat(text,image,text_cross) @ W1 + b1) -> tf32
    k_tc2<1, 3><<<dim3(8, 32), 256, TC_SMEM_BYTES>>>(
        xin_p, xin_p + 4096ul * 1024ul, tc_p, w_p + 4ul * MW,
        b1, b1, b1, (float*)0, 3072);

    // 6) comp_out = hidden @ W2 + b2
    k_tc2<0, 0><<<dim3(8, 32), 256, TC_SMEM_BYTES>>>(
        hid_p, (const uint32_t*)0, (const uint32_t*)0, w_p + 7ul * MW,
        b2, b2, b2, out + 8388608, 1024);
}

// round 14
// speedup vs baseline: 3.2960x; 1.0198x over previous
#include <cuda_runtime.h>
#include <math.h>
#include <stdint.h>

// ---------------------------------------------------------------------------
// Problem constants
//   B=8, L=512, D=1024, H=16, DH=64
//   outputs: text_cross[4M] | image_cross[4M] | comp_out[4M] | avg_attn[2M]
// ---------------------------------------------------------------------------

#define NELEM_PROJ (4194304ul)            // B*H*L*DH
#define MW (1048576ul)                    // 1024*1024

// scratch (device globals: allocation-free rule). tf32 payloads as uint32.
__device__ uint32_t g_xin_tf[8192ul * 1024ul];      // [text(4096);image(4096)][1024]
__device__ uint32_t g_w_tf[8ul * MW];               // Wq|Wk|Wv|Wo|W1(3M)|W2
__device__ uint32_t g_proj[6ul * NELEM_PROJ];       // [src(2)][proj(3)][b,h,l,dh] tf32
__device__ float    g_S[128ul * 512ul * 512ul];     // [bh][q][k] unnormalized exp (dir0)
__device__ float    g_denom[128ul * 512ul];         // [bh][q]
__device__ uint32_t g_ctx_tf[2ul * NELEM_PROJ];     // [dir][b*512+l][1024] tf32
__device__ uint32_t g_tc_tf[NELEM_PROJ];            // text_cross tf32
__device__ uint32_t g_hidden_tf[NELEM_PROJ];        // [4096][1024] tf32

// ---------------------------------------------------------------------------
// helpers
// ---------------------------------------------------------------------------
__device__ __forceinline__ uint32_t f2tf32(float f) {
    uint32_t u;
    asm("cvt.rna.tf32.f32 %0, %1;" : "=r"(u) : "f"(f));
    return u;
}
__device__ __forceinline__ uint32_t sptr(const void* p) {
    return (uint32_t)__cvta_generic_to_shared(p);
}
__device__ __forceinline__ void cp16(uint32_t s, const void* g) {
    asm volatile("cp.async.cg.shared.global [%0], [%1], 16;" :: "r"(s), "l"(g));
}
#define CP_COMMIT() asm volatile("cp.async.commit_group;")
#define CP_WAIT2()  asm volatile("cp.async.wait_group 2;" ::: "memory")

#define MMA_TF32(d, a, b)                                                     \
    asm volatile(                                                             \
        "mma.sync.aligned.m16n8k8.row.col.f32.tf32.tf32.f32 "                 \
        "{%0,%1,%2,%3}, {%4,%5,%6,%7}, {%8,%9}, {%0,%1,%2,%3};"               \
        : "+f"(d[0]), "+f"(d[1]), "+f"(d[2]), "+f"(d[3])                      \
        : "r"(a[0]), "r"(a[1]), "r"(a[2]), "r"(a[3]), "r"(b[0]), "r"(b[1]))

// ---------------------------------------------------------------------------
// k_cvt_all: one launch converts inputs + all weights fp32 -> tf32.
// grid (4096, 8); segment = blockIdx.y. n4 = element_count / 4 (float4 units).
//   text/image: 4,194,304 el -> 1,048,576 float4
//   Wq/Wk/Wv/Wo/W2: 1,048,576 el -> 262,144 float4
//   W1: 3,145,728 el -> 786,432 float4
// ---------------------------------------------------------------------------
__global__ __launch_bounds__(256) void k_cvt_all(
    const float* __restrict__ text, const float* __restrict__ image,
    const float* __restrict__ Wq, const float* __restrict__ Wk,
    const float* __restrict__ Wv, const float* __restrict__ Wo,
    const float* __restrict__ W1, const float* __restrict__ W2)
{
    const int seg = blockIdx.y;
    const float* src;
    uint32_t* dst;
    int n4;
    switch (seg) {
        case 0: src = text;  dst = g_xin_tf;                 n4 = 1048576; break;
        case 1: src = image; dst = g_xin_tf + 4194304ul;     n4 = 1048576; break;
        case 2: src = Wq;    dst = g_w_tf;                   n4 = 262144;  break;
        case 3: src = Wk;    dst = g_w_tf + 1ul * MW;        n4 = 262144;  break;
        case 4: src = Wv;    dst = g_w_tf + 2ul * MW;        n4 = 262144;  break;
        case 5: src = Wo;    dst = g_w_tf + 3ul * MW;        n4 = 262144;  break;
        case 6: src = W1;    dst = g_w_tf + 4ul * MW;        n4 = 786432;  break;
        default: src = W2;   dst = g_w_tf + 7ul * MW;        n4 = 262144;  break;
    }
    const int i = blockIdx.x * 256 + threadIdx.x;
    if (i < n4) {
        float4 v = ((const float4*)src)[i];
        uint4 u;
        u.x = f2tf32(v.x); u.y = f2tf32(v.y);
        u.z = f2tf32(v.z); u.w = f2tf32(v.w);
        ((uint4*)dst)[i] = u;
    }
}

// ---------------------------------------------------------------------------
// Tensor-core tf32 GEMM, BM=BN=128, BK=16, 256 threads (8 warps, 4m x 2n),
// warp tile 32x64, mma m16n8k8. A and W already tf32 in global (uint32).
// 4-stage cp.async ring, single __syncthreads per k-iteration.
//   AMODE 0: A = A0[M][1024]
//   AMODE 1: K=3072 concat: k<1024 -> A0, <2048 -> A1, else A2 (each [M][1024])
//   EMODE 0: C fp32 = acc + bias                  (W2, final)
//   EMODE 1: proj: sigmoid for bsel<2, scatter tf32 into g_proj head layout
//   EMODE 2: Wo: C fp32 = acc + bias, and tf32 copy to g_tc_tf for rows<4096
//   EMODE 3: FFN1: relu, tf32 only to g_hidden_tf
// EMODE1: grid.x=24, bsel=x>>3 picks W at Wbase + bsel*1M and bias.
// Dynamic smem: As[4][128][20] + Bs[4][16][136] = 75776 bytes.
// ---------------------------------------------------------------------------
#define TC_SMEM_BYTES 75776

template<int AMODE, int EMODE>
__global__ __launch_bounds__(256, 2) void k_tc2(
    const uint32_t* __restrict__ A0, const uint32_t* __restrict__ A1,
    const uint32_t* __restrict__ A2, const uint32_t* __restrict__ Wbase,
    const float* __restrict__ ba, const float* __restrict__ bb,
    const float* __restrict__ bc,
    float* __restrict__ C, int K)
{
    extern __shared__ uint32_t smem_tc[];
    uint32_t (*As)[128][20] = (uint32_t(*)[128][20])smem_tc;
    uint32_t (*Bs)[16][136] = (uint32_t(*)[16][136])(smem_tc + 4 * 128 * 20);

    const int tid  = threadIdx.x;
    const int wid  = tid >> 5, lane = tid & 31;
    const int gid  = lane >> 2, tig = lane & 3;
    const int wm   = (wid & 3) * 32;
    const int wn   = (wid >> 2) * 64;

    int bsel = 0, n0;
    const uint32_t* W;
    const float* bias;
    if (EMODE == 1) {
        bsel = blockIdx.x >> 3;
        n0   = (blockIdx.x & 7) * 128;
        W    = Wbase + (size_t)bsel * MW;
        bias = (bsel == 0) ? ba : (bsel == 1 ? bb : bc);
    } else {
        n0 = blockIdx.x * 128;
        W = Wbase; bias = ba;
    }
    const int m0 = blockIdx.y * 128;

    float acc[2][8][4];
    #pragma unroll
    for (int i = 0; i < 2; ++i)
        #pragma unroll
        for (int j = 0; j < 8; ++j)
            #pragma unroll
            for (int q = 0; q < 4; ++q) acc[i][j][q] = 0.f;

    const int T = K >> 4;

    auto load_stage = [&](int st, int k0) {
        #pragma unroll
        for (int i = 0; i < 2; ++i) {
            const int c = tid + i * 256;          // 0..511
            const int arow = c >> 2, akc = c & 3;
            const uint32_t* ga;
            if (AMODE == 1) {
                const int seg = k0 >> 10;
                const uint32_t* base = (seg == 0) ? A0 : (seg == 1 ? A1 : A2);
                ga = base + (size_t)(m0 + arow) * 1024 + (k0 & 1023) + akc * 4;
            } else {
                ga = A0 + (size_t)(m0 + arow) * 1024 + k0 + akc * 4;
            }
            cp16(sptr(&As[st][arow][akc * 4]), ga);
            const int bkr = c >> 5, bnc = c & 31;
            cp16(sptr(&Bs[st][bkr][bnc * 4]),
                 W + (size_t)(k0 + bkr) * 1024 + n0 + bnc * 4);
        }
    };

    // prologue: stages 0, 1, 2
    load_stage(0, 0);  CP_COMMIT();
    load_stage(1, 16); CP_COMMIT();
    load_stage(2, 32); CP_COMMIT();

    for (int t = 0; t < T; ++t) {
        CP_WAIT2();              // stage t resident (<=2 newer groups pending)
        __syncthreads();         // data visible + everyone done with buf (t+3)&3

        if (t + 3 < T) load_stage((t + 3) & 3, (t + 3) * 16);
        CP_COMMIT();

        const int buf = t & 3;
        #pragma unroll
        for (int kk = 0; kk < 16; kk += 8) {
            uint32_t af[2][4], bf[8][2];
            #pragma unroll
            for (int tm = 0; tm < 2; ++tm) {
                const int mb = wm + tm * 16;
                af[tm][0] = As[buf][mb + gid    ][kk + tig    ];
                af[tm][1] = As[buf][mb + gid + 8][kk + tig    ];
                af[tm][2] = As[buf][mb + gid    ][kk + tig + 4];
                af[tm][3] = As[buf][mb + gid + 8][kk + tig + 4];
            }
            #pragma unroll
            for (int tn = 0; tn < 8; ++tn) {
                const int nb = wn + tn * 8;
                bf[tn][0] = Bs[buf][kk + tig    ][nb + gid];
                bf[tn][1] = Bs[buf][kk + tig + 4][nb + gid];
            }
            #pragma unroll
            for (int tm = 0; tm < 2; ++tm)
                #pragma unroll
                for (int tn = 0; tn < 8; ++tn)
                    MMA_TF32(acc[tm][tn], af[tm], bf[tn]);
        }
    }

    // ---- epilogue ----
    if (EMODE == 0 || EMODE == 2) {
        #pragma unroll
        for (int tm = 0; tm < 2; ++tm) {
            #pragma unroll
            for (int tn = 0; tn < 8; ++tn) {
                const int r = m0 + wm + tm * 16 + gid;
                const int c = n0 + wn + tn * 8 + 2 * tig;
                float v0 = acc[tm][tn][0] + bias[c];
                float v1 = acc[tm][tn][1] + bias[c + 1];
                float v2 = acc[tm][tn][2] + bias[c];
                float v3 = acc[tm][tn][3] + bias[c + 1];
                *(float2*)&C[(size_t)r * 1024 + c]       = make_float2(v0, v1);
                *(float2*)&C[(size_t)(r + 8) * 1024 + c] = make_float2(v2, v3);
                if (EMODE == 2 && m0 < 4096) {
                    uint2 u0; u0.x = f2tf32(v0); u0.y = f2tf32(v1);
                    uint2 u1; u1.x = f2tf32(v2); u1.y = f2tf32(v3);
                    *(uint2*)&g_tc_tf[(size_t)r * 1024 + c]       = u0;
                    *(uint2*)&g_tc_tf[(size_t)(r + 8) * 1024 + c] = u1;
                }
            }
        }
    } else if (EMODE == 3) {
        #pragma unroll
        for (int tm = 0; tm < 2; ++tm) {
            #pragma unroll
            for (int tn = 0; tn < 8; ++tn) {
                const int r = m0 + wm + tm * 16 + gid;
                const int c = n0 + wn + tn * 8 + 2 * tig;
                uint2 u0, u1;
                u0.x = f2tf32(fmaxf(acc[tm][tn][0] + bias[c],     0.f));
                u0.y = f2tf32(fmaxf(acc[tm][tn][1] + bias[c + 1], 0.f));
                u1.x = f2tf32(fmaxf(acc[tm][tn][2] + bias[c],     0.f));
                u1.y = f2tf32(fmaxf(acc[tm][tn][3] + bias[c + 1], 0.f));
                *(uint2*)&g_hidden_tf[(size_t)r * 1024 + c]       = u0;
                *(uint2*)&g_hidden_tf[(size_t)(r + 8) * 1024 + c] = u1;
            }
        }
    } else {  // EMODE 1: proj
        const int src = m0 >> 12;
        uint32_t* dst = g_proj + (size_t)(src * 3 + bsel) * NELEM_PROJ;
        #pragma unroll
        for (int tm = 0; tm < 2; ++tm) {
            #pragma unroll
            for (int tn = 0; tn < 8; ++tn) {
                const int m  = m0 + wm + tm * 16 + gid;
                const int lr = m & 4095;
                const int bidx = lr >> 9;
                const int l    = lr & 511;
                const int nl = n0 + wn + tn * 8 + 2 * tig;
                const int h = nl >> 6, dh = nl & 63;
                float v0 = acc[tm][tn][0] + bias[nl];
                float v1 = acc[tm][tn][1] + bias[nl + 1];
                float v2 = acc[tm][tn][2] + bias[nl];
                float v3 = acc[tm][tn][3] + bias[nl + 1];
                if (bsel < 2) {
                    v0 = 1.f / (1.f + __expf(-v0));
                    v1 = 1.f / (1.f + __expf(-v1));
                    v2 = 1.f / (1.f + __expf(-v2));
                    v3 = 1.f / (1.f + __expf(-v3));
                }
                uint2 u0; u0.x = f2tf32(v0); u0.y = f2tf32(v1);
                uint2 u1; u1.x = f2tf32(v2); u1.y = f2tf32(v3);
                const size_t base0 = (size_t)((bidx * 16 + h) * 512 + l) * 64 + dh;
                const size_t base1 = (size_t)((bidx * 16 + h) * 512 + l + 8) * 64 + dh;
                *(uint2*)&dst[base0] = u0;
                *(uint2*)&dst[base1] = u1;
            }
        }
    }
}

// ---------------------------------------------------------------------------
// Fused flash attention (legacy tf32 mma path — unchanged, known good).
// ---------------------------------------------------------------------------
#define ATTN_SMEM_BYTES 87296

__global__ __launch_bounds__(256) void k_attn()
{
    extern __shared__ uint32_t sm[];
    uint32_t* Qs  = sm;            // stride 68
    uint32_t* KPs = sm + 4352;     // Ks stride 68 / Ps stride 132
    uint32_t* Vs  = sm + 13056;    // stride 68
    float* rowsum = (float*)(sm + 21760);

    const int tid = threadIdx.x;
    const int wid = tid >> 5, lane = tid & 31;
    const int gid = lane >> 2, tig = lane & 3;
    const int wm  = (wid & 3) * 16;
    const int wns = (wid >> 2) * 64;
    const int wno = (wid >> 2) * 32;

    const int qt = blockIdx.x, bh = blockIdx.y, dir = blockIdx.z;
    const int q0 = qt * 64;

    const int q_src = dir ? 1 : 0, k_src = dir ? 0 : 1;
    const uint32_t* __restrict__ Qg = g_proj + (size_t)(q_src * 3 + 0) * NELEM_PROJ
                                      + (size_t)bh * 512 * 64;
    const uint32_t* __restrict__ Kg = g_proj + (size_t)(k_src * 3 + 1) * NELEM_PROJ
                                      + (size_t)bh * 512 * 64;
    const uint32_t* __restrict__ Vg = g_proj + (size_t)(k_src * 3 + 2) * NELEM_PROJ
                                      + (size_t)bh * 512 * 64;

    if (tid < 64) rowsum[tid] = 0.f;

    #pragma unroll
    for (int i = 0; i < 4; ++i) {
        const int f = tid + i * 256;
        const int row = f >> 4, c4 = (f & 15) * 4;
        *(uint4*)&Qs[row * 68 + c4] = *(const uint4*)(Qg + (size_t)(q0 + row) * 64 + c4);
    }

    float accO[4][4];
    #pragma unroll
    for (int tn = 0; tn < 4; ++tn)
        #pragma unroll
        for (int q = 0; q < 4; ++q) accO[tn][q] = 0.f;
    float sum0 = 0.f, sum1 = 0.f;

    for (int kc = 0; kc < 4; ++kc) {
        const int s0 = kc * 128;

        #pragma unroll
        for (int i = 0; i < 8; ++i) {
            const int f = tid + i * 256;
            const int row = f >> 4, c4 = (f & 15) * 4;
            *(uint4*)&KPs[row * 68 + c4] =
                *(const uint4*)(Kg + (size_t)(s0 + row) * 64 + c4);
            *(uint4*)&Vs[row * 68 + c4] =
                *(const uint4*)(Vg + (size_t)(s0 + row) * 64 + c4);
        }
        __syncthreads();

        float accS[8][4];
        #pragma unroll
        for (int tn = 0; tn < 8; ++tn)
            #pragma unroll
            for (int q = 0; q < 4; ++q) accS[tn][q] = 0.f;

        #pragma unroll
        for (int kk = 0; kk < 64; kk += 8) {
            uint32_t af[4];
            af[0] = Qs[(wm + gid    ) * 68 + kk + tig    ];
            af[1] = Qs[(wm + gid + 8) * 68 + kk + tig    ];
            af[2] = Qs[(wm + gid    ) * 68 + kk + tig + 4];
            af[3] = Qs[(wm + gid + 8) * 68 + kk + tig + 4];
            #pragma unroll
            for (int tn = 0; tn < 8; ++tn) {
                const int nb = wns + tn * 8;
                uint32_t bf[2];
                bf[0] = KPs[(nb + gid) * 68 + kk + tig    ];
                bf[1] = KPs[(nb + gid) * 68 + kk + tig + 4];
                MMA_TF32(accS[tn], af, bf);
            }
        }
        __syncthreads();

        #pragma unroll
        for (int tn = 0; tn < 8; ++tn) {
            const float p0 = __expf(accS[tn][0] * 0.015625f);
            const float p1 = __expf(accS[tn][1] * 0.015625f);
            const float p2 = __expf(accS[tn][2] * 0.015625f);
            const float p3 = __expf(accS[tn][3] * 0.015625f);
            sum0 += p0 + p1;
            sum1 += p2 + p3;
            const int c  = wns + tn * 8 + 2 * tig;
            const int r0 = wm + gid, r1 = wm + gid + 8;
            uint2 u0; u0.x = f2tf32(p0); u0.y = f2tf32(p1);
            uint2 u1; u1.x = f2tf32(p2); u1.y = f2tf32(p3);
            *(uint2*)&KPs[r0 * 132 + c] = u0;
            *(uint2*)&KPs[r1 * 132 + c] = u1;
            if (dir == 0) {
                float* Sg = g_S + (size_t)bh * 262144;
                *(float2*)&Sg[(size_t)(q0 + r0) * 512 + s0 + c] = make_float2(p0, p1);
                *(float2*)&Sg[(size_t)(q0 + r1) * 512 + s0 + c] = make_float2(p2, p3);
            }
        }
        __syncthreads();

        #pragma unroll
        for (int kk = 0; kk < 128; kk += 8) {
            uint32_t af[4];
            af[0] = KPs[(wm + gid    ) * 132 + kk + tig    ];
            af[1] = KPs[(wm + gid + 8) * 132 + kk + tig    ];
            af[2] = KPs[(wm + gid    ) * 132 + kk + tig + 4];
            af[3] = KPs[(wm + gid + 8) * 132 + kk + tig + 4];
            #pragma unroll
            for (int tn = 0; tn < 4; ++tn) {
                const int nb = wno + tn * 8;
                uint32_t bf[2];
                bf[0] = Vs[(kk + tig    ) * 68 + nb + gid];
                bf[1] = Vs[(kk + tig + 4) * 68 + nb + gid];
                MMA_TF32(accO[tn], af, bf);
            }
        }
        __syncthreads();
    }

    sum0 += __shfl_xor_sync(0xffffffffu, sum0, 1);
    sum0 += __shfl_xor_sync(0xffffffffu, sum0, 2);
    sum1 += __shfl_xor_sync(0xffffffffu, sum1, 1);
    sum1 += __shfl_xor_sync(0xffffffffu, sum1, 2);
    if (tig == 0) {
        atomicAdd(&rowsum[wm + gid    ], sum0);
        atomicAdd(&rowsum[wm + gid + 8], sum1);
    }
    __syncthreads();

    const int b = bh >> 4, h = bh & 15;
    uint32_t* dst = g_ctx_tf + (size_t)dir * NELEM_PROJ;
    const float inv0 = 1.f / rowsum[wm + gid];
    const float inv1 = 1.f / rowsum[wm + gid + 8];
    #pragma unroll
    for (int tn = 0; tn < 4; ++tn) {
        const int dh = wno + tn * 8 + 2 * tig;
        const int l0 = q0 + wm + gid, l1 = l0 + 8;
        uint2 u0, u1;
        u0.x = f2tf32(accO[tn][0] * inv0); u0.y = f2tf32(accO[tn][1] * inv0);
        u1.x = f2tf32(accO[tn][2] * inv1); u1.y = f2tf32(accO[tn][3] * inv1);
        *(uint2*)&dst[(size_t)(b * 512 + l0) * 1024 + h * 64 + dh] = u0;
        *(uint2*)&dst[(size_t)(b * 512 + l1) * 1024 + h * 64 + dh] = u1;
    }

    if (dir == 0 && tid < 64)
        g_denom[(size_t)bh * 512 + q0 + tid] = rowsum[tid];
}

// ---------------------------------------------------------------------------
// avg_attn[b][q][k] = (1/16) sum_h expS[bh][q][k] / denom[bh][q]
// ---------------------------------------------------------------------------
__global__ __launch_bounds__(256) void k_avg(float* __restrict__ out)
{
    const int e = blockIdx.x * 256 + threadIdx.x;
    const int b = e >> 18;
    const int r = e & 262143;
    const int q = r >> 9;
    float s = 0.f;
    #pragma unroll
    for (int h = 0; h < 16; ++h) {
        const float d = g_denom[(size_t)(b * 16 + h) * 512 + q];
        s += g_S[(size_t)(b * 16 + h) * 262144 + r] * __frcp_rn(d);
    }
    out[e] = s * 0.0625f;
}

// ---------------------------------------------------------------------------
// launch
// ---------------------------------------------------------------------------
extern "C" void kernel_launch(void* const* d_in, const int* in_sizes, int n_in,
                              void* d_out, int out_size)
{
    const float* text  = (const float*)d_in[0];
    const float* image = (const float*)d_in[1];
    const float* Wq = (const float*)d_in[2];
    const float* bq = (const float*)d_in[3];
    const float* Wk = (const float*)d_in[4];
    const float* bk = (const float*)d_in[5];
    const float* Wv = (const float*)d_in[6];
    const float* bv = (const float*)d_in[7];
    const float* Wo = (const float*)d_in[8];
    const float* bo = (const float*)d_in[9];
    const float* W1 = (const float*)d_in[10];
    const float* b1 = (const float*)d_in[11];
    const float* W2 = (const float*)d_in[12];
    const float* b2 = (const float*)d_in[13];
    float* out = (float*)d_out;

    uint32_t *xin_p = 0, *w_p = 0, *ctx_p = 0, *tc_p = 0, *hid_p = 0;
    cudaGetSymbolAddress((void**)&xin_p, g_xin_tf);
    cudaGetSymbolAddress((void**)&w_p,   g_w_tf);
    cudaGetSymbolAddress((void**)&ctx_p, g_ctx_tf);
    cudaGetSymbolAddress((void**)&tc_p,  g_tc_tf);
    cudaGetSymbolAddress((void**)&hid_p, g_hidden_tf);

    cudaFuncSetAttribute(k_attn, cudaFuncAttributeMaxDynamicSharedMemorySize,
                         ATTN_SMEM_BYTES);
    cudaFuncSetAttribute(k_tc2<0, 1>, cudaFuncAttributeMaxDynamicSharedMemorySize,
                         TC_SMEM_BYTES);
    cudaFuncSetAttribute(k_tc2<0, 2>, cudaFuncAttributeMaxDynamicSharedMemorySize,
                         TC_SMEM_BYTES);
    cudaFuncSetAttribute(k_tc2<1, 3>, cudaFuncAttributeMaxDynamicSharedMemorySize,
                         TC_SMEM_BYTES);
    cudaFuncSetAttribute(k_tc2<0, 0>, cudaFuncAttributeMaxDynamicSharedMemorySize,
                         TC_SMEM_BYTES);

    // 0) convert inputs + weights to tf32 (single launch, 8 segments)
    k_cvt_all<<<dim3(4096, 8), 256>>>(text, image, Wq, Wk, Wv, Wo, W1, W2);

    // 1) fused QKV projections (both modalities) + sigmoid -> g_proj (tf32)
    k_tc2<0, 1><<<dim3(24, 64), 256, TC_SMEM_BYTES>>>(
        xin_p, (const uint32_t*)0, (const uint32_t*)0, w_p,
        bq, bk, bv, (float*)0, 1024);

    // 2) fused flash attention, both directions
    k_attn<<<dim3(8, 128, 2), 256, ATTN_SMEM_BYTES>>>();

    // 3) avg_attn from dir-0 unnormalized probs + denominators
    k_avg<<<8192, 256>>>(out + 12582912);

    // 4) output projection -> d_out (fp32) + text_cross tf32 copy
    k_tc2<0, 2><<<dim3(8, 64), 256, TC_SMEM_BYTES>>>(
        ctx_p, (const uint32_t*)0, (const uint32_t*)0, w_p + 3ul * MW,
        bo, bo, bo, out, 1024);

    // 5) FFN1: hidden = relu(concat(text,image,text_cross) @ W1 + b1) -> tf32
    k_tc2<1, 3><<<dim3(8, 32), 256, TC_SMEM_BYTES>>>(
        xin_p, xin_p + 4096ul * 1024ul, tc_p, w_p + 4ul * MW,
        b1, b1, b1, (float*)0, 3072);

    // 6) comp_out = hidden @ W2 + b2
    k_tc2<0, 0><<<dim3(8, 32), 256, TC_SMEM_BYTES>>>(
        hid_p, (const uint32_t*)0, (const uint32_t*)0, w_p + 7ul * MW,
        b2, b2, b2, out + 8388608, 1024);
}

// round 15
// speedup vs baseline: 3.4728x; 1.0537x over previous
#include <cuda_runtime.h>
#include <cuda_fp16.h>
#include <math.h>
#include <stdint.h>

// ---------------------------------------------------------------------------
// Problem constants
//   B=8, L=512, D=1024, H=16, DH=64
//   outputs: text_cross[4M] | image_cross[4M] | comp_out[4M] | avg_attn[2M]
// ---------------------------------------------------------------------------

#define NELEM_PROJ (4194304ul)            // B*H*L*DH
#define MW (1048576ul)                    // 1024*1024

// scratch (device globals: allocation-free rule). tf32 payloads as uint32.
__device__ uint32_t g_xin_tf[8192ul * 1024ul];      // [text(4096);image(4096)][1024]
__device__ uint32_t g_w_tf[8ul * MW];               // Wq|Wk|Wv|Wo|W1(3M)|W2
__device__ uint32_t g_proj[6ul * NELEM_PROJ];       // [src(2)][proj(3)][b,h,l,dh] tf32
__device__ __half   g_S_h[128ul * 512ul * 512ul];   // [bh][q][k] unnormalized exp (dir0)
__device__ float    g_denom[128ul * 512ul];         // [bh][q]
__device__ uint32_t g_ctx_tf[2ul * NELEM_PROJ];     // [dir][b*512+l][1024] tf32
__device__ uint32_t g_tc_tf[NELEM_PROJ];            // text_cross tf32
__device__ uint32_t g_hidden_tf[NELEM_PROJ];        // [4096][1024] tf32

// ---------------------------------------------------------------------------
// helpers
// ---------------------------------------------------------------------------
__device__ __forceinline__ uint32_t f2tf32(float f) {
    uint32_t u;
    asm("cvt.rna.tf32.f32 %0, %1;" : "=r"(u) : "f"(f));
    return u;
}
__device__ __forceinline__ uint32_t sptr(const void* p) {
    return (uint32_t)__cvta_generic_to_shared(p);
}
__device__ __forceinline__ void cp16(uint32_t s, const void* g) {
    asm volatile("cp.async.cg.shared.global [%0], [%1], 16;" :: "r"(s), "l"(g));
}
#define CP_COMMIT() asm volatile("cp.async.commit_group;")
#define CP_WAIT1()  asm volatile("cp.async.wait_group 1;" ::: "memory")

#define MMA_TF32(d, a, b)                                                     \
    asm volatile(                                                             \
        "mma.sync.aligned.m16n8k8.row.col.f32.tf32.tf32.f32 "                 \
        "{%0,%1,%2,%3}, {%4,%5,%6,%7}, {%8,%9}, {%0,%1,%2,%3};"               \
        : "+f"(d[0]), "+f"(d[1]), "+f"(d[2]), "+f"(d[3])                      \
        : "r"(a[0]), "r"(a[1]), "r"(a[2]), "r"(a[3]), "r"(b[0]), "r"(b[1]))

// ---------------------------------------------------------------------------
// k_cvt_all: one launch converts inputs + all weights fp32 -> tf32.
// grid (4096, 8); segment = blockIdx.y. n4 = element_count / 4.
// ---------------------------------------------------------------------------
__global__ __launch_bounds__(256) void k_cvt_all(
    const float* __restrict__ text, const float* __restrict__ image,
    const float* __restrict__ Wq, const float* __restrict__ Wk,
    const float* __restrict__ Wv, const float* __restrict__ Wo,
    const float* __restrict__ W1, const float* __restrict__ W2)
{
    const int seg = blockIdx.y;
    const float* src;
    uint32_t* dst;
    int n4;
    switch (seg) {
        case 0: src = text;  dst = g_xin_tf;                 n4 = 1048576; break;
        case 1: src = image; dst = g_xin_tf + 4194304ul;     n4 = 1048576; break;
        case 2: src = Wq;    dst = g_w_tf;                   n4 = 262144;  break;
        case 3: src = Wk;    dst = g_w_tf + 1ul * MW;        n4 = 262144;  break;
        case 4: src = Wv;    dst = g_w_tf + 2ul * MW;        n4 = 262144;  break;
        case 5: src = Wo;    dst = g_w_tf + 3ul * MW;        n4 = 262144;  break;
        case 6: src = W1;    dst = g_w_tf + 4ul * MW;        n4 = 786432;  break;
        default: src = W2;   dst = g_w_tf + 7ul * MW;        n4 = 262144;  break;
    }
    const int i = blockIdx.x * 256 + threadIdx.x;
    if (i < n4) {
        float4 v = ((const float4*)src)[i];
        uint4 u;
        u.x = f2tf32(v.x); u.y = f2tf32(v.y);
        u.z = f2tf32(v.z); u.w = f2tf32(v.w);
        ((uint4*)dst)[i] = u;
    }
}

// ---------------------------------------------------------------------------
// Tensor-core tf32 GEMM, BM=BN=128, BK=16, 256 threads (8 warps, 4m x 2n),
// warp tile 32x64, mma m16n8k8. 6-stage cp.async ring, TWO stages per loop
// body committed as ONE group -> one __syncthreads per 32 k (half the
// barriers of the 4-stage version).
//   AMODE 0: A = A0[M][1024]
//   AMODE 1: K=3072 concat: k<1024 -> A0, <2048 -> A1, else A2 (each [M][1024])
//   EMODE 0: C fp32 = acc + bias                  (W2, final)
//   EMODE 1: proj: sigmoid for bsel<2, scatter tf32 into g_proj head layout
//   EMODE 2: Wo: C fp32 = acc + bias, and tf32 copy to g_tc_tf for rows<4096
//   EMODE 3: FFN1: relu, tf32 only to g_hidden_tf
// Dynamic smem: As[6][128][20] + Bs[6][16][136] = 113664 bytes (2 CTA/SM).
// ---------------------------------------------------------------------------
#define TC_SMEM_BYTES 113664

template<int AMODE, int EMODE>
__global__ __launch_bounds__(256, 2) void k_tc2(
    const uint32_t* __restrict__ A0, const uint32_t* __restrict__ A1,
    const uint32_t* __restrict__ A2, const uint32_t* __restrict__ Wbase,
    const float* __restrict__ ba, const float* __restrict__ bb,
    const float* __restrict__ bc,
    float* __restrict__ C, int K)
{
    extern __shared__ uint32_t smem_tc[];
    uint32_t (*As)[128][20] = (uint32_t(*)[128][20])smem_tc;
    uint32_t (*Bs)[16][136] = (uint32_t(*)[16][136])(smem_tc + 6 * 128 * 20);

    const int tid  = threadIdx.x;
    const int wid  = tid >> 5, lane = tid & 31;
    const int gid  = lane >> 2, tig = lane & 3;
    const int wm   = (wid & 3) * 32;
    const int wn   = (wid >> 2) * 64;

    int bsel = 0, n0;
    const uint32_t* W;
    const float* bias;
    if (EMODE == 1) {
        bsel = blockIdx.x >> 3;
        n0   = (blockIdx.x & 7) * 128;
        W    = Wbase + (size_t)bsel * MW;
        bias = (bsel == 0) ? ba : (bsel == 1 ? bb : bc);
    } else {
        n0 = blockIdx.x * 128;
        W = Wbase; bias = ba;
    }
    const int m0 = blockIdx.y * 128;

    float acc[2][8][4];
    #pragma unroll
    for (int i = 0; i < 2; ++i)
        #pragma unroll
        for (int j = 0; j < 8; ++j)
            #pragma unroll
            for (int q = 0; q < 4; ++q) acc[i][j][q] = 0.f;

    const int T  = K >> 4;     // 16-k stages
    const int TT = T >> 1;     // pairs (K multiple of 32 always)

    auto load_stage = [&](int st, int k0) {
        #pragma unroll
        for (int i = 0; i < 2; ++i) {
            const int c = tid + i * 256;          // 0..511
            const int arow = c >> 2, akc = c & 3;
            const uint32_t* ga;
            if (AMODE == 1) {
                const int seg = k0 >> 10;
                const uint32_t* base = (seg == 0) ? A0 : (seg == 1 ? A1 : A2);
                ga = base + (size_t)(m0 + arow) * 1024 + (k0 & 1023) + akc * 4;
            } else {
                ga = A0 + (size_t)(m0 + arow) * 1024 + k0 + akc * 4;
            }
            cp16(sptr(&As[st][arow][akc * 4]), ga);
            const int bkr = c >> 5, bnc = c & 31;
            cp16(sptr(&Bs[st][bkr][bnc * 4]),
                 W + (size_t)(k0 + bkr) * 1024 + n0 + bnc * 4);
        }
    };

    // prologue: group0 = stages 0,1 ; group1 = stages 2,3
    load_stage(0, 0);  load_stage(1, 16); CP_COMMIT();
    load_stage(2, 32); load_stage(3, 48); CP_COMMIT();

    for (int tt = 0; tt < TT; ++tt) {
        CP_WAIT1();              // group tt resident (<=1 newer group pending)
        __syncthreads();         // visible + everyone done with stages 2tt-2,2tt-1

        const int s0 = 2 * tt + 4;
        if (s0 < T) { load_stage(s0 % 6, s0 * 16); load_stage((s0 + 1) % 6, (s0 + 1) * 16); }
        CP_COMMIT();

        #pragma unroll
        for (int half = 0; half < 2; ++half) {
            const int buf = (2 * tt + half) % 6;
            #pragma unroll
            for (int kk = 0; kk < 16; kk += 8) {
                uint32_t af[2][4], bf[8][2];
                #pragma unroll
                for (int tm = 0; tm < 2; ++tm) {
                    const int mb = wm + tm * 16;
                    af[tm][0] = As[buf][mb + gid    ][kk + tig    ];
                    af[tm][1] = As[buf][mb + gid + 8][kk + tig    ];
                    af[tm][2] = As[buf][mb + gid    ][kk + tig + 4];
                    af[tm][3] = As[buf][mb + gid + 8][kk + tig + 4];
                }
                #pragma unroll
                for (int tn = 0; tn < 8; ++tn) {
                    const int nb = wn + tn * 8;
                    bf[tn][0] = Bs[buf][kk + tig    ][nb + gid];
                    bf[tn][1] = Bs[buf][kk + tig + 4][nb + gid];
                }
                #pragma unroll
                for (int tm = 0; tm < 2; ++tm)
                    #pragma unroll
                    for (int tn = 0; tn < 8; ++tn)
                        MMA_TF32(acc[tm][tn], af[tm], bf[tn]);
            }
        }
    }

    // ---- epilogue ----
    if (EMODE == 0 || EMODE == 2) {
        #pragma unroll
        for (int tm = 0; tm < 2; ++tm) {
            #pragma unroll
            for (int tn = 0; tn < 8; ++tn) {
                const int r = m0 + wm + tm * 16 + gid;
                const int c = n0 + wn + tn * 8 + 2 * tig;
                float v0 = acc[tm][tn][0] + bias[c];
                float v1 = acc[tm][tn][1] + bias[c + 1];
                float v2 = acc[tm][tn][2] + bias[c];
                float v3 = acc[tm][tn][3] + bias[c + 1];
                *(float2*)&C[(size_t)r * 1024 + c]       = make_float2(v0, v1);
                *(float2*)&C[(size_t)(r + 8) * 1024 + c] = make_float2(v2, v3);
                if (EMODE == 2 && m0 < 4096) {
                    uint2 u0; u0.x = f2tf32(v0); u0.y = f2tf32(v1);
                    uint2 u1; u1.x = f2tf32(v2); u1.y = f2tf32(v3);
                    *(uint2*)&g_tc_tf[(size_t)r * 1024 + c]       = u0;
                    *(uint2*)&g_tc_tf[(size_t)(r + 8) * 1024 + c] = u1;
                }
            }
        }
    } else if (EMODE == 3) {
        #pragma unroll
        for (int tm = 0; tm < 2; ++tm) {
            #pragma unroll
            for (int tn = 0; tn < 8; ++tn) {
                const int r = m0 + wm + tm * 16 + gid;
                const int c = n0 + wn + tn * 8 + 2 * tig;
                uint2 u0, u1;
                u0.x = f2tf32(fmaxf(acc[tm][tn][0] + bias[c],     0.f));
                u0.y = f2tf32(fmaxf(acc[tm][tn][1] + bias[c + 1], 0.f));
                u1.x = f2tf32(fmaxf(acc[tm][tn][2] + bias[c],     0.f));
                u1.y = f2tf32(fmaxf(acc[tm][tn][3] + bias[c + 1], 0.f));
                *(uint2*)&g_hidden_tf[(size_t)r * 1024 + c]       = u0;
                *(uint2*)&g_hidden_tf[(size_t)(r + 8) * 1024 + c] = u1;
            }
        }
    } else {  // EMODE 1: proj
        const int src = m0 >> 12;
        uint32_t* dst = g_proj + (size_t)(src * 3 + bsel) * NELEM_PROJ;
        #pragma unroll
        for (int tm = 0; tm < 2; ++tm) {
            #pragma unroll
            for (int tn = 0; tn < 8; ++tn) {
                const int m  = m0 + wm + tm * 16 + gid;
                const int lr = m & 4095;
                const int bidx = lr >> 9;
                const int l    = lr & 511;
                const int nl = n0 + wn + tn * 8 + 2 * tig;
                const int h = nl >> 6, dh = nl & 63;
                float v0 = acc[tm][tn][0] + bias[nl];
                float v1 = acc[tm][tn][1] + bias[nl + 1];
                float v2 = acc[tm][tn][2] + bias[nl];
                float v3 = acc[tm][tn][3] + bias[nl + 1];
                if (bsel < 2) {
                    v0 = 1.f / (1.f + __expf(-v0));
                    v1 = 1.f / (1.f + __expf(-v1));
                    v2 = 1.f / (1.f + __expf(-v2));
                    v3 = 1.f / (1.f + __expf(-v3));
                }
                uint2 u0; u0.x = f2tf32(v0); u0.y = f2tf32(v1);
                uint2 u1; u1.x = f2tf32(v2); u1.y = f2tf32(v3);
                const size_t base0 = (size_t)((bidx * 16 + h) * 512 + l) * 64 + dh;
                const size_t base1 = (size_t)((bidx * 16 + h) * 512 + l + 8) * 64 + dh;
                *(uint2*)&dst[base0] = u0;
                *(uint2*)&dst[base1] = u1;
            }
        }
    }
}

// ---------------------------------------------------------------------------
// Fused flash attention (legacy tf32 mma). dir0 spills exp(S) as fp16.
// ---------------------------------------------------------------------------
#define ATTN_SMEM_BYTES 87296

__global__ __launch_bounds__(256) void k_attn()
{
    extern __shared__ uint32_t sm[];
    uint32_t* Qs  = sm;            // stride 68
    uint32_t* KPs = sm + 4352;     // Ks stride 68 / Ps stride 132
    uint32_t* Vs  = sm + 13056;    // stride 68
    float* rowsum = (float*)(sm + 21760);

    const int tid = threadIdx.x;
    const int wid = tid >> 5, lane = tid & 31;
    const int gid = lane >> 2, tig = lane & 3;
    const int wm  = (wid & 3) * 16;
    const int wns = (wid >> 2) * 64;
    const int wno = (wid >> 2) * 32;

    const int qt = blockIdx.x, bh = blockIdx.y, dir = blockIdx.z;
    const int q0 = qt * 64;

    const int q_src = dir ? 1 : 0, k_src = dir ? 0 : 1;
    const uint32_t* __restrict__ Qg = g_proj + (size_t)(q_src * 3 + 0) * NELEM_PROJ
                                      + (size_t)bh * 512 * 64;
    const uint32_t* __restrict__ Kg = g_proj + (size_t)(k_src * 3 + 1) * NELEM_PROJ
                                      + (size_t)bh * 512 * 64;
    const uint32_t* __restrict__ Vg = g_proj + (size_t)(k_src * 3 + 2) * NELEM_PROJ
                                      + (size_t)bh * 512 * 64;

    if (tid < 64) rowsum[tid] = 0.f;

    #pragma unroll
    for (int i = 0; i < 4; ++i) {
        const int f = tid + i * 256;
        const int row = f >> 4, c4 = (f & 15) * 4;
        *(uint4*)&Qs[row * 68 + c4] = *(const uint4*)(Qg + (size_t)(q0 + row) * 64 + c4);
    }

    float accO[4][4];
    #pragma unroll
    for (int tn = 0; tn < 4; ++tn)
        #pragma unroll
        for (int q = 0; q < 4; ++q) accO[tn][q] = 0.f;
    float sum0 = 0.f, sum1 = 0.f;

    for (int kc = 0; kc < 4; ++kc) {
        const int s0 = kc * 128;

        #pragma unroll
        for (int i = 0; i < 8; ++i) {
            const int f = tid + i * 256;
            const int row = f >> 4, c4 = (f & 15) * 4;
            *(uint4*)&KPs[row * 68 + c4] =
                *(const uint4*)(Kg + (size_t)(s0 + row) * 64 + c4);
            *(uint4*)&Vs[row * 68 + c4] =
                *(const uint4*)(Vg + (size_t)(s0 + row) * 64 + c4);
        }
        __syncthreads();

        float accS[8][4];
        #pragma unroll
        for (int tn = 0; tn < 8; ++tn)
            #pragma unroll
            for (int q = 0; q < 4; ++q) accS[tn][q] = 0.f;

        #pragma unroll
        for (int kk = 0; kk < 64; kk += 8) {
            uint32_t af[4];
            af[0] = Qs[(wm + gid    ) * 68 + kk + tig    ];
            af[1] = Qs[(wm + gid + 8) * 68 + kk + tig    ];
            af[2] = Qs[(wm + gid    ) * 68 + kk + tig + 4];
            af[3] = Qs[(wm + gid + 8) * 68 + kk + tig + 4];
            #pragma unroll
            for (int tn = 0; tn < 8; ++tn) {
                const int nb = wns + tn * 8;
                uint32_t bf[2];
                bf[0] = KPs[(nb + gid) * 68 + kk + tig    ];
                bf[1] = KPs[(nb + gid) * 68 + kk + tig + 4];
                MMA_TF32(accS[tn], af, bf);
            }
        }
        __syncthreads();

        #pragma unroll
        for (int tn = 0; tn < 8; ++tn) {
            const float p0 = __expf(accS[tn][0] * 0.015625f);
            const float p1 = __expf(accS[tn][1] * 0.015625f);
            const float p2 = __expf(accS[tn][2] * 0.015625f);
            const float p3 = __expf(accS[tn][3] * 0.015625f);
            sum0 += p0 + p1;
            sum1 += p2 + p3;
            const int c  = wns + tn * 8 + 2 * tig;
            const int r0 = wm + gid, r1 = wm + gid + 8;
            uint2 u0; u0.x = f2tf32(p0); u0.y = f2tf32(p1);
            uint2 u1; u1.x = f2tf32(p2); u1.y = f2tf32(p3);
            *(uint2*)&KPs[r0 * 132 + c] = u0;
            *(uint2*)&KPs[r1 * 132 + c] = u1;
            if (dir == 0) {
                __half* Sg = g_S_h + (size_t)bh * 262144;
                *(__half2*)&Sg[(size_t)(q0 + r0) * 512 + s0 + c] =
                    __floats2half2_rn(p0, p1);
                *(__half2*)&Sg[(size_t)(q0 + r1) * 512 + s0 + c] =
                    __floats2half2_rn(p2, p3);
            }
        }
        __syncthreads();

        #pragma unroll
        for (int kk = 0; kk < 128; kk += 8) {
            uint32_t af[4];
            af[0] = KPs[(wm + gid    ) * 132 + kk + tig    ];
            af[1] = KPs[(wm + gid + 8) * 132 + kk + tig    ];
            af[2] = KPs[(wm + gid    ) * 132 + kk + tig + 4];
            af[3] = KPs[(wm + gid + 8) * 132 + kk + tig + 4];
            #pragma unroll
            for (int tn = 0; tn < 4; ++tn) {
                const int nb = wno + tn * 8;
                uint32_t bf[2];
                bf[0] = Vs[(kk + tig    ) * 68 + nb + gid];
                bf[1] = Vs[(kk + tig + 4) * 68 + nb + gid];
                MMA_TF32(accO[tn], af, bf);
            }
        }
        __syncthreads();
    }

    sum0 += __shfl_xor_sync(0xffffffffu, sum0, 1);
    sum0 += __shfl_xor_sync(0xffffffffu, sum0, 2);
    sum1 += __shfl_xor_sync(0xffffffffu, sum1, 1);
    sum1 += __shfl_xor_sync(0xffffffffu, sum1, 2);
    if (tig == 0) {
        atomicAdd(&rowsum[wm + gid    ], sum0);
        atomicAdd(&rowsum[wm + gid + 8], sum1);
    }
    __syncthreads();

    const int b = bh >> 4, h = bh & 15;
    uint32_t* dst = g_ctx_tf + (size_t)dir * NELEM_PROJ;
    const float inv0 = 1.f / rowsum[wm + gid];
    const float inv1 = 1.f / rowsum[wm + gid + 8];
    #pragma unroll
    for (int tn = 0; tn < 4; ++tn) {
        const int dh = wno + tn * 8 + 2 * tig;
        const int l0 = q0 + wm + gid, l1 = l0 + 8;
        uint2 u0, u1;
        u0.x = f2tf32(accO[tn][0] * inv0); u0.y = f2tf32(accO[tn][1] * inv0);
        u1.x = f2tf32(accO[tn][2] * inv1); u1.y = f2tf32(accO[tn][3] * inv1);
        *(uint2*)&dst[(size_t)(b * 512 + l0) * 1024 + h * 64 + dh] = u0;
        *(uint2*)&dst[(size_t)(b * 512 + l1) * 1024 + h * 64 + dh] = u1;
    }

    if (dir == 0 && tid < 64)
        g_denom[(size_t)bh * 512 + q0 + tid] = rowsum[tid];
}

// ---------------------------------------------------------------------------
// avg_attn[b][q][k] = (1/16) sum_h expS[bh][q][k] / denom[bh][q]
// 4 elements per thread (uint2 = 4 fp16 per head), float4 store.
// ---------------------------------------------------------------------------
__global__ __launch_bounds__(256) void k_avg(float* __restrict__ out)
{
    const int e4 = blockIdx.x * 256 + threadIdx.x;   // 524,288 threads
    const int e  = e4 * 4;
    const int b  = e >> 18;
    const int r  = e & 262143;                        // 4-aligned
    const int q  = r >> 9;
    float s0 = 0.f, s1 = 0.f, s2 = 0.f, s3 = 0.f;
    #pragma unroll
    for (int h = 0; h < 16; ++h) {
        const float inv = __frcp_rn(g_denom[(size_t)(b * 16 + h) * 512 + q]);
        const uint2 u = *(const uint2*)(g_S_h + (size_t)(b * 16 + h) * 262144 + r);
        const float2 f01 = __half22float2(*(const __half2*)&u.x);
        const float2 f23 = __half22float2(*(const __half2*)&u.y);
        s0 += f01.x * inv; s1 += f01.y * inv;
        s2 += f23.x * inv; s3 += f23.y * inv;
    }
    float4 o;
    o.x = s0 * 0.0625f; o.y = s1 * 0.0625f;
    o.z = s2 * 0.0625f; o.w = s3 * 0.0625f;
    *(float4*)&out[e] = o;
}

// ---------------------------------------------------------------------------
// launch
// ---------------------------------------------------------------------------
extern "C" void kernel_launch(void* const* d_in, const int* in_sizes, int n_in,
                              void* d_out, int out_size)
{
    const float* text  = (const float*)d_in[0];
    const float* image = (const float*)d_in[1];
    const float* Wq = (const float*)d_in[2];
    const float* bq = (const float*)d_in[3];
    const float* Wk = (const float*)d_in[4];
    const float* bk = (const float*)d_in[5];
    const float* Wv = (const float*)d_in[6];
    const float* bv = (const float*)d_in[7];
    const float* Wo = (const float*)d_in[8];
    const float* bo = (const float*)d_in[9];
    const float* W1 = (const float*)d_in[10];
    const float* b1 = (const float*)d_in[11];
    const float* W2 = (const float*)d_in[12];
    const float* b2 = (const float*)d_in[13];
    float* out = (float*)d_out;

    uint32_t *xin_p = 0, *w_p = 0, *ctx_p = 0, *tc_p = 0, *hid_p = 0;
    cudaGetSymbolAddress((void**)&xin_p, g_xin_tf);
    cudaGetSymbolAddress((void**)&w_p,   g_w_tf);
    cudaGetSymbolAddress((void**)&ctx_p, g_ctx_tf);
    cudaGetSymbolAddress((void**)&tc_p,  g_tc_tf);
    cudaGetSymbolAddress((void**)&hid_p, g_hidden_tf);

    cudaFuncSetAttribute(k_attn, cudaFuncAttributeMaxDynamicSharedMemorySize,
                         ATTN_SMEM_BYTES);
    cudaFuncSetAttribute(k_tc2<0, 1>, cudaFuncAttributeMaxDynamicSharedMemorySize,
                         TC_SMEM_BYTES);
    cudaFuncSetAttribute(k_tc2<0, 2>, cudaFuncAttributeMaxDynamicSharedMemorySize,
                         TC_SMEM_BYTES);
    cudaFuncSetAttribute(k_tc2<1, 3>, cudaFuncAttributeMaxDynamicSharedMemorySize,
                         TC_SMEM_BYTES);
    cudaFuncSetAttribute(k_tc2<0, 0>, cudaFuncAttributeMaxDynamicSharedMemorySize,
                         TC_SMEM_BYTES);

    // 0) convert inputs + weights to tf32 (single launch, 8 segments)
    k_cvt_all<<<dim3(4096, 8), 256>>>(text, image, Wq, Wk, Wv, Wo, W1, W2);

    // 1) fused QKV projections (both modalities) + sigmoid -> g_proj (tf32)
    k_tc2<0, 1><<<dim3(24, 64), 256, TC_SMEM_BYTES>>>(
        xin_p, (const uint32_t*)0, (const uint32_t*)0, w_p,
        bq, bk, bv, (float*)0, 1024);

    // 2) fused flash attention, both directions
    k_attn<<<dim3(8, 128, 2), 256, ATTN_SMEM_BYTES>>>();

    // 3) avg_attn from dir-0 unnormalized probs (fp16) + denominators
    k_avg<<<2048, 256>>>(out + 12582912);

    // 4) output projection -> d_out (fp32) + text_cross tf32 copy
    k_tc2<0, 2><<<dim3(8, 64), 256, TC_SMEM_BYTES>>>(
        ctx_p, (const uint32_t*)0, (const uint32_t*)0, w_p + 3ul * MW,
        bo, bo, bo, out, 1024);

    // 5) FFN1: hidden = relu(concat(text,image,text_cross) @ W1 + b1) -> tf32
    k_tc2<1, 3><<<dim3(8, 32), 256, TC_SMEM_BYTES>>>(
        xin_p, xin_p + 4096ul * 1024ul, tc_p, w_p + 4ul * MW,
        b1, b1, b1, (float*)0, 3072);

    // 6) comp_out = hidden @ W2 + b2
    k_tc2<0, 0><<<dim3(8, 32), 256, TC_SMEM_BYTES>>>(
        hid_p, (const uint32_t*)0, (const uint32_t*)0, w_p + 7ul * MW,
        b2, b2, b2, out + 8388608, 1024);
}